// round 1
// baseline (speedup 1.0000x reference)
#include <cuda_runtime.h>
#include <math.h>

#define BATCH 8192
#define D_IN  1024
#define SIZE  64
#define NN    (SIZE * SIZE)   // 4096

// ---------------------------------------------------------------------------
// Scratch (static __device__ arrays: no allocation allowed)
// ---------------------------------------------------------------------------
__device__ float g_Ha[(size_t)BATCH * D_IN];      // 32 MB
__device__ float g_Hb[(size_t)BATCH * D_IN];      // 32 MB
__device__ float g_Lg[(size_t)BATCH * NN];        // 128 MB
__device__ float g_D2[(size_t)BATCH * SIZE];      // 2 MB

// ---------------------------------------------------------------------------
// SGEMM: C[M,N] = act(A[M,K] @ B[K,N] + bias[N]),  act = relu if RELU
// Tiles: 128x128x16, 256 threads, 8x8 per thread, register prefetch.
// M % 128 == 0, N % 128 == 0, K % 16 == 0 assumed.
// ---------------------------------------------------------------------------
template <bool RELU>
__global__ __launch_bounds__(256, 2) void sgemm_bias(
    const float* __restrict__ A, const float* __restrict__ B,
    const float* __restrict__ bias, float* __restrict__ C,
    int M, int N, int K)
{
    constexpr int BM = 128, BN = 128, BK = 16;
    __shared__ float As[BK][BM];   // transposed
    __shared__ float Bs[BK][BN];

    const int tid  = threadIdx.x;
    const int trow = (tid >> 4) << 3;   // 0..120
    const int tcol = (tid & 15) << 3;   // 0..120
    const size_t aRow0 = (size_t)blockIdx.y * BM;
    const int    cCol0 = blockIdx.x * BN;

    float acc[8][8];
#pragma unroll
    for (int i = 0; i < 8; i++)
#pragma unroll
        for (int j = 0; j < 8; j++) acc[i][j] = 0.f;

    float4 aReg[2], bReg[2];

    // ---- prefetch tile 0 ----
#pragma unroll
    for (int l = 0; l < 2; l++) {
        int idx = l * 256 + tid;
        int r = idx >> 2, c = (idx & 3) << 2;             // A: 128 rows x 16
        aReg[l] = *(const float4*)(A + (aRow0 + r) * (size_t)K + c);
        int r2 = idx >> 5, c2 = (idx & 31) << 2;          // B: 16 rows x 128
        bReg[l] = *(const float4*)(B + (size_t)r2 * N + cCol0 + c2);
    }
#pragma unroll
    for (int l = 0; l < 2; l++) {
        int idx = l * 256 + tid;
        int r = idx >> 2, c = (idx & 3) << 2;
        As[c + 0][r] = aReg[l].x; As[c + 1][r] = aReg[l].y;
        As[c + 2][r] = aReg[l].z; As[c + 3][r] = aReg[l].w;
        int r2 = idx >> 5, c2 = (idx & 31) << 2;
        *(float4*)&Bs[r2][c2] = bReg[l];
    }
    __syncthreads();

    for (int k0 = BK; k0 <= K; k0 += BK) {
        // prefetch next tile into registers (overlaps with compute)
        if (k0 < K) {
#pragma unroll
            for (int l = 0; l < 2; l++) {
                int idx = l * 256 + tid;
                int r = idx >> 2, c = (idx & 3) << 2;
                aReg[l] = *(const float4*)(A + (aRow0 + r) * (size_t)K + k0 + c);
                int r2 = idx >> 5, c2 = (idx & 31) << 2;
                bReg[l] = *(const float4*)(B + (size_t)(k0 + r2) * N + cCol0 + c2);
            }
        }

#pragma unroll
        for (int kk = 0; kk < BK; kk++) {
            float a[8], b[8];
            *(float4*)(a)     = *(float4*)&As[kk][trow];
            *(float4*)(a + 4) = *(float4*)&As[kk][trow + 4];
            *(float4*)(b)     = *(float4*)&Bs[kk][tcol];
            *(float4*)(b + 4) = *(float4*)&Bs[kk][tcol + 4];
#pragma unroll
            for (int i = 0; i < 8; i++)
#pragma unroll
                for (int j = 0; j < 8; j++)
                    acc[i][j] = fmaf(a[i], b[j], acc[i][j]);
        }
        __syncthreads();

        if (k0 < K) {
#pragma unroll
            for (int l = 0; l < 2; l++) {
                int idx = l * 256 + tid;
                int r = idx >> 2, c = (idx & 3) << 2;
                As[c + 0][r] = aReg[l].x; As[c + 1][r] = aReg[l].y;
                As[c + 2][r] = aReg[l].z; As[c + 3][r] = aReg[l].w;
                int r2 = idx >> 5, c2 = (idx & 31) << 2;
                *(float4*)&Bs[r2][c2] = bReg[l];
            }
            __syncthreads();
        }
    }

    // ---- epilogue: bias (+relu), vectorized stores ----
    float bv[8];
#pragma unroll
    for (int j = 0; j < 8; j++) bv[j] = bias[cCol0 + tcol + j];

#pragma unroll
    for (int i = 0; i < 8; i++) {
        size_t gr = aRow0 + trow + i;
        float v[8];
#pragma unroll
        for (int j = 0; j < 8; j++) {
            float t = acc[i][j] + bv[j];
            if (RELU) t = fmaxf(t, 0.f);
            v[j] = t;
        }
        *(float4*)(C + gr * N + cCol0 + tcol)     = *(float4*)(v);
        *(float4*)(C + gr * N + cCol0 + tcol + 4) = *(float4*)(v + 4);
    }
}

// ---------------------------------------------------------------------------
// d2 branch: d2 = softmax(Hb @ W2b + b2b) over the 64-wide axis.
// One CTA = 32 rows; 256 threads; thread = (row, 8-col group).
// ---------------------------------------------------------------------------
__global__ __launch_bounds__(256) void gemm_d2_softmax(
    const float* __restrict__ Hb, const float* __restrict__ W2b,
    const float* __restrict__ b2b, float* __restrict__ d2)
{
    __shared__ float As[32][33];   // +1 pad: conflict-free As[r][kk]
    __shared__ float Bs[32][64];

    const int row0 = blockIdx.x * 32;
    const int tid  = threadIdx.x;
    const int r    = tid >> 3;          // 0..31
    const int cg   = (tid & 7) << 3;    // 0,8,...,56

    float acc[8];
#pragma unroll
    for (int j = 0; j < 8; j++) acc[j] = 0.f;

    for (int k0 = 0; k0 < D_IN; k0 += 32) {
        {   // As: 32 rows x 32 k (one float4 per thread)
            int rr = tid >> 3, cc = (tid & 7) << 2;
            float4 t = *(const float4*)(Hb + (size_t)(row0 + rr) * D_IN + k0 + cc);
            As[rr][cc + 0] = t.x; As[rr][cc + 1] = t.y;
            As[rr][cc + 2] = t.z; As[rr][cc + 3] = t.w;
        }
#pragma unroll
        for (int l = 0; l < 2; l++) {   // Bs: 32 k x 64 n
            int idx = l * 256 + tid;
            int rr = idx >> 4, cc = (idx & 15) << 2;
            *(float4*)&Bs[rr][cc] = *(const float4*)(W2b + (size_t)(k0 + rr) * SIZE + cc);
        }
        __syncthreads();
#pragma unroll
        for (int kk = 0; kk < 32; kk++) {
            float a = As[r][kk];
#pragma unroll
            for (int j = 0; j < 8; j++)
                acc[j] = fmaf(a, Bs[kk][cg + j], acc[j]);
        }
        __syncthreads();
    }

#pragma unroll
    for (int j = 0; j < 8; j++) acc[j] += b2b[cg + j];

    // softmax across the row: 8 consecutive lanes own one row (8 vals each)
    float m = -1e30f;
#pragma unroll
    for (int j = 0; j < 8; j++) m = fmaxf(m, acc[j]);
#pragma unroll
    for (int o = 4; o > 0; o >>= 1) m = fmaxf(m, __shfl_xor_sync(0xffffffffu, m, o));

    float e[8], s = 0.f;
#pragma unroll
    for (int j = 0; j < 8; j++) { e[j] = expf(acc[j] - m); s += e[j]; }
#pragma unroll
    for (int o = 4; o > 0; o >>= 1) s += __shfl_xor_sync(0xffffffffu, s, o);
    float inv = 1.0f / s;

    float v[8];
#pragma unroll
    for (int j = 0; j < 8; j++) v[j] = e[j] * inv;
    *(float4*)(d2 + (size_t)(row0 + r) * SIZE + cg)     = *(float4*)(v);
    *(float4*)(d2 + (size_t)(row0 + r) * SIZE + cg + 4) = *(float4*)(v + 4);
}

// ---------------------------------------------------------------------------
// Finalize: per row b — softmax over 4096 logits, then
// out[b,y] = max_x min(p[b,x,y], d2[b,x]).  One CTA (256 thr) per row.
// ---------------------------------------------------------------------------
__global__ __launch_bounds__(256) void finalize(
    const float* __restrict__ logits, const float* __restrict__ d2,
    float* __restrict__ out)
{
    __shared__ float sl[NN];     // 16 KB: exp(logit - m) staged
    __shared__ float sred[8];
    __shared__ float sd[SIZE];

    const int b = blockIdx.x, tid = threadIdx.x;
    const float4* lrow = (const float4*)(logits + (size_t)b * NN);

    // pass 1: stage + row max
    float lm = -1e30f;
#pragma unroll
    for (int l = 0; l < 4; l++) {
        int j = tid + l * 256;
        float4 t = lrow[j];
        *(float4*)&sl[4 * j] = t;
        lm = fmaxf(lm, fmaxf(fmaxf(t.x, t.y), fmaxf(t.z, t.w)));
    }
#pragma unroll
    for (int o = 16; o > 0; o >>= 1) lm = fmaxf(lm, __shfl_xor_sync(0xffffffffu, lm, o));
    if ((tid & 31) == 0) sred[tid >> 5] = lm;
    __syncthreads();
    if (tid < 32) {
        float v2 = (tid < 8) ? sred[tid] : -1e30f;
#pragma unroll
        for (int o = 4; o > 0; o >>= 1) v2 = fmaxf(v2, __shfl_xor_sync(0xffffffffu, v2, o));
        if (tid == 0) sred[0] = v2;
    }
    __syncthreads();
    const float m = sred[0];
    __syncthreads();   // protect sred reuse below

    // pass 2: exp in place + row sum
    float ls = 0.f;
#pragma unroll
    for (int l = 0; l < 4; l++) {
        int j = tid + l * 256;
        float4 t = *(float4*)&sl[4 * j];
        t.x = expf(t.x - m); t.y = expf(t.y - m);
        t.z = expf(t.z - m); t.w = expf(t.w - m);
        *(float4*)&sl[4 * j] = t;
        ls += t.x + t.y + t.z + t.w;
    }
#pragma unroll
    for (int o = 16; o > 0; o >>= 1) ls += __shfl_xor_sync(0xffffffffu, ls, o);
    if ((tid & 31) == 0) sred[tid >> 5] = ls;
    __syncthreads();
    if (tid < 32) {
        float v2 = (tid < 8) ? sred[tid] : 0.f;
#pragma unroll
        for (int o = 4; o > 0; o >>= 1) v2 += __shfl_xor_sync(0xffffffffu, v2, o);
        if (tid == 0) sred[0] = v2;
    }
    if (tid < SIZE) sd[tid] = d2[(size_t)b * SIZE + tid];
    __syncthreads();
    const float inv = 1.0f / sred[0];

    // join: out[y] = max_x min(sl[x*64+y]*inv, sd[x])
    if (tid < SIZE) {
        float best = -1e30f;
#pragma unroll 8
        for (int x = 0; x < SIZE; x++)
            best = fmaxf(best, fminf(sl[x * SIZE + tid] * inv, sd[x]));
        out[(size_t)b * SIZE + tid] = best;
    }
}

// ---------------------------------------------------------------------------
// Launch
// ---------------------------------------------------------------------------
extern "C" void kernel_launch(void* const* d_in, const int* in_sizes, int n_in,
                              void* d_out, int out_size)
{
    const float* x   = (const float*)d_in[0];
    const float* W1a = (const float*)d_in[1];
    const float* b1a = (const float*)d_in[2];
    const float* W2a = (const float*)d_in[3];
    const float* b2a = (const float*)d_in[4];
    const float* W1b = (const float*)d_in[5];
    const float* b1b = (const float*)d_in[6];
    const float* W2b = (const float*)d_in[7];
    const float* b2b = (const float*)d_in[8];
    float* out = (float*)d_out;

    float *Ha, *Hb, *Lg, *D2;
    cudaGetSymbolAddress((void**)&Ha, g_Ha);
    cudaGetSymbolAddress((void**)&Hb, g_Hb);
    cudaGetSymbolAddress((void**)&Lg, g_Lg);
    cudaGetSymbolAddress((void**)&D2, g_D2);

    dim3 g1(D_IN / 128, BATCH / 128);       // 8 x 64
    sgemm_bias<true><<<g1, 256>>>(x, W1a, b1a, Ha, BATCH, D_IN, D_IN);
    sgemm_bias<true><<<g1, 256>>>(x, W1b, b1b, Hb, BATCH, D_IN, D_IN);

    dim3 g2(NN / 128, BATCH / 128);         // 32 x 64
    sgemm_bias<false><<<g2, 256>>>(Ha, W2a, b2a, Lg, BATCH, NN, D_IN);

    gemm_d2_softmax<<<BATCH / 32, 256>>>(Hb, W2b, b2b, D2);
    finalize<<<BATCH, 256>>>(Lg, D2, out);
}

// round 3
// speedup vs baseline: 2.2367x; 2.2367x over previous
#include <cuda_runtime.h>
#include <cuda_bf16.h>
#include <math.h>
#include <stdint.h>

#define BATCH 8192
#define D_IN  1024
#define SIZE  64
#define NN    4096

typedef __nv_bfloat16  bf16;
typedef __nv_bfloat162 bf162;

// ---------------------------------------------------------------------------
// Scratch (__device__ globals; no allocation allowed)
// ---------------------------------------------------------------------------
__device__ __align__(16) bf16 g_Xh [(size_t)BATCH * D_IN];
__device__ __align__(16) bf16 g_Xl [(size_t)BATCH * D_IN];
__device__ __align__(16) bf16 g_W1aTh[(size_t)D_IN * D_IN];
__device__ __align__(16) bf16 g_W1aTl[(size_t)D_IN * D_IN];
__device__ __align__(16) bf16 g_W1bTh[(size_t)D_IN * D_IN];
__device__ __align__(16) bf16 g_W1bTl[(size_t)D_IN * D_IN];
__device__ __align__(16) bf16 g_W2aTh[(size_t)NN * D_IN];
__device__ __align__(16) bf16 g_W2aTl[(size_t)NN * D_IN];
__device__ __align__(16) bf16 g_W2bTh[(size_t)SIZE * D_IN];
__device__ __align__(16) bf16 g_W2bTl[(size_t)SIZE * D_IN];
__device__ __align__(16) bf16 g_Hah[(size_t)BATCH * D_IN];
__device__ __align__(16) bf16 g_Hal[(size_t)BATCH * D_IN];
__device__ __align__(16) bf16 g_Hbh[(size_t)BATCH * D_IN];
__device__ __align__(16) bf16 g_Hbl[(size_t)BATCH * D_IN];
__device__ __align__(16) float g_Lg [(size_t)BATCH * NN];
__device__ __align__(16) float g_Dlog[(size_t)BATCH * SIZE];
__device__ __align__(16) float g_D2 [(size_t)BATCH * SIZE];

// ---------------------------------------------------------------------------
// PTX helpers (all target-portable: sm_80+)
// ---------------------------------------------------------------------------
__device__ __forceinline__ uint32_t smem_u32(const void* p) {
    uint32_t a;
    asm("{ .reg .u64 t; cvta.to.shared.u64 t, %1; cvt.u32.u64 %0, t; }"
        : "=r"(a) : "l"(p));
    return a;
}

#define CP16(dst, src) \
    asm volatile("cp.async.cg.shared.global [%0], [%1], 16;" :: "r"(dst), "l"(src) : "memory")
#define CP_COMMIT() asm volatile("cp.async.commit_group;" ::: "memory")
#define CP_WAIT(n)  asm volatile("cp.async.wait_group %0;" :: "n"(n) : "memory")

#define LDSM4(r0, r1, r2, r3, a) \
    asm volatile("ldmatrix.sync.aligned.m8n8.x4.shared.b16 {%0,%1,%2,%3}, [%4];" \
                 : "=r"(r0), "=r"(r1), "=r"(r2), "=r"(r3) : "r"(a))

#define MMA16816(d, a, b) \
    asm volatile("mma.sync.aligned.m16n8k16.row.col.f32.bf16.bf16.f32 " \
                 "{%0,%1,%2,%3}, {%4,%5,%6,%7}, {%8,%9}, {%0,%1,%2,%3};" \
                 : "+f"((d)[0]), "+f"((d)[1]), "+f"((d)[2]), "+f"((d)[3]) \
                 : "r"((a)[0]), "r"((a)[1]), "r"((a)[2]), "r"((a)[3]), \
                   "r"((b)[0]), "r"((b)[1]))

// ---------------------------------------------------------------------------
// Split-bf16 MMA GEMM:  C[M, Ntot] = act((Ah+Al) @ (Bh+Bl)^T + bias)
// A: [M, 1024] K-major bf16 hi/lo.  B: [Ntot, 1024] K-major bf16 hi/lo.
// CTA tile 128 x BN, BK=32, 3-stage cp.async pipeline, 256 threads.
// Warp grid 2(M) x 4(N): warp tile 64 x (BN/4).
// ---------------------------------------------------------------------------
template <int BN, bool RELU, bool OUTSPLIT>
__global__ __launch_bounds__(256, 1) void mma_gemm(
    const bf16* __restrict__ Ahg, const bf16* __restrict__ Alg,
    const bf16* __restrict__ Bhg, const bf16* __restrict__ Blg,
    const float* __restrict__ bias,
    float* __restrict__ Cf, bf16* __restrict__ Ch, bf16* __restrict__ Cl,
    int Ntot)
{
    constexpr int BM = 128, S = 3;
    constexpr int NCHUNK = D_IN / 32;            // 32 k-chunks of 32
    constexpr int ROWP = 40;                      // bf16/row: 32 data + 8 pad
    constexpr int AE = BM * ROWP;                 // bf16 per A array
    constexpr int BE = BN * ROWP;
    constexpr int STAGE = 2 * AE + 2 * BE;        // bf16 per stage
    constexpr int ACH = BM * 4;                   // 16B chunks per A array
    constexpr int BCH = BN * 4;
    constexpr int NCHK = 2 * ACH + 2 * BCH;       // chunks per stage
    constexpr int NFRAG = BN / 32;                // n-frags per warp (4 or 2)
    constexpr int WNT = BN / 4;                   // warp n-tile

    extern __shared__ __align__(16) bf16 sm[];

    const int tid = threadIdx.x, lane = tid & 31, wid = tid >> 5;
    const int warp_m = wid & 1, warp_n = wid >> 1;
    const int m0 = blockIdx.y * BM, n0 = blockIdx.x * BN;
    const uint32_t sbase = smem_u32(sm);

    // ---- loader: chunk c -> (smem offset bf16, gmem ptr) ----
    auto issue_stage = [&](int i) {
        const int k0 = i * 32;
        const uint32_t sb = sbase + (uint32_t)(i % S) * STAGE * 2;
#pragma unroll
        for (int p = 0; p < (NCHK + 255) / 256; p++) {
            int c = tid + p * 256;
            if (c < NCHK) {
                const bf16* g;
                uint32_t soff;
                if (c < ACH) {
                    int r = c >> 2, kc = c & 3;
                    g = Ahg + (size_t)(m0 + r) * D_IN + k0 + kc * 8;
                    soff = (uint32_t)(r * ROWP + kc * 8);
                } else if (c < 2 * ACH) {
                    int cc = c - ACH, r = cc >> 2, kc = cc & 3;
                    g = Alg + (size_t)(m0 + r) * D_IN + k0 + kc * 8;
                    soff = (uint32_t)(AE + r * ROWP + kc * 8);
                } else if (c < 2 * ACH + BCH) {
                    int cc = c - 2 * ACH, r = cc >> 2, kc = cc & 3;
                    g = Bhg + (size_t)(n0 + r) * D_IN + k0 + kc * 8;
                    soff = (uint32_t)(2 * AE + r * ROWP + kc * 8);
                } else {
                    int cc = c - 2 * ACH - BCH, r = cc >> 2, kc = cc & 3;
                    g = Blg + (size_t)(n0 + r) * D_IN + k0 + kc * 8;
                    soff = (uint32_t)(2 * AE + BE + r * ROWP + kc * 8);
                }
                CP16(sb + soff * 2, (const char*)g);
            }
        }
    };

    float acc[4][NFRAG][4];
#pragma unroll
    for (int f = 0; f < 4; f++)
#pragma unroll
        for (int n = 0; n < NFRAG; n++)
#pragma unroll
            for (int q = 0; q < 4; q++) acc[f][n][q] = 0.f;

    // per-lane ldmatrix row components
    const int aRow = warp_m * 64 + (lane & 15);      // + f*16
    const int aKl  = (lane >> 4) << 3;               // 0 or 8
    const int bRow = warp_n * WNT + (lane & 7) + ((lane >> 4) << 3);  // + p*16
    const int bKl  = ((lane >> 3) & 1) << 3;

    // ---- prologue: stages 0..S-2 ----
#pragma unroll
    for (int i = 0; i < S - 1; i++) { issue_stage(i); CP_COMMIT(); }

    for (int i = 0; i < NCHUNK; i++) {
        CP_WAIT(S - 2);
        __syncthreads();

        if (i + S - 1 < NCHUNK) issue_stage(i + S - 1);
        CP_COMMIT();

        const uint32_t sb = sbase + (uint32_t)(i % S) * STAGE * 2;
#pragma unroll
        for (int k16 = 0; k16 < 32; k16 += 16) {
            uint32_t ah[4][4], al[4][4], bh[NFRAG][2], bl[NFRAG][2];
#pragma unroll
            for (int f = 0; f < 4; f++) {
                uint32_t ra = sb + (uint32_t)(((aRow + f * 16) * ROWP) + k16 + aKl) * 2;
                LDSM4(ah[f][0], ah[f][1], ah[f][2], ah[f][3], ra);
                LDSM4(al[f][0], al[f][1], al[f][2], al[f][3], ra + AE * 2);
            }
#pragma unroll
            for (int p = 0; p < NFRAG / 2; p++) {
                uint32_t rb = sb + (uint32_t)(2 * AE + (bRow + p * 16) * ROWP + k16 + bKl) * 2;
                LDSM4(bh[2 * p][0], bh[2 * p][1], bh[2 * p + 1][0], bh[2 * p + 1][1], rb);
                LDSM4(bl[2 * p][0], bl[2 * p][1], bl[2 * p + 1][0], bl[2 * p + 1][1], rb + BE * 2);
            }
#pragma unroll
            for (int f = 0; f < 4; f++)
#pragma unroll
                for (int n = 0; n < NFRAG; n++) {
                    MMA16816(acc[f][n], ah[f], bh[n]);
                    MMA16816(acc[f][n], ah[f], bl[n]);
                    MMA16816(acc[f][n], al[f], bh[n]);
                }
        }
    }

    // ---- epilogue: stage C through smem for coalesced stores ----
    __syncthreads();                                  // all warps done with pipeline smem
    constexpr int P = BN + 4;
    float* smC = reinterpret_cast<float*>(sm);
#pragma unroll
    for (int f = 0; f < 4; f++)
#pragma unroll
        for (int n = 0; n < NFRAG; n++) {
            int r = warp_m * 64 + f * 16 + (lane >> 2);
            int c = warp_n * WNT + n * 8 + 2 * (lane & 3);
            *reinterpret_cast<float2*>(&smC[r * P + c]) =
                make_float2(acc[f][n][0], acc[f][n][1]);
            *reinterpret_cast<float2*>(&smC[(r + 8) * P + c]) =
                make_float2(acc[f][n][2], acc[f][n][3]);
        }
    __syncthreads();

    constexpr int C4 = BN / 4;                        // float4 per row
#pragma unroll
    for (int u = 0; u < BM * C4 / 256; u++) {
        int idx = tid + u * 256;
        int r = idx / C4, c4 = idx % C4;
        float4 v = *reinterpret_cast<float4*>(&smC[r * P + c4 * 4]);
        int col = n0 + c4 * 4;
        v.x += bias[col]; v.y += bias[col + 1]; v.z += bias[col + 2]; v.w += bias[col + 3];
        if (RELU) {
            v.x = fmaxf(v.x, 0.f); v.y = fmaxf(v.y, 0.f);
            v.z = fmaxf(v.z, 0.f); v.w = fmaxf(v.w, 0.f);
        }
        size_t go = (size_t)(m0 + r) * Ntot + col;
        if (OUTSPLIT) {
            bf16 h0 = __float2bfloat16(v.x), h1 = __float2bfloat16(v.y);
            bf16 h2 = __float2bfloat16(v.z), h3 = __float2bfloat16(v.w);
            bf16 l0 = __float2bfloat16(v.x - __bfloat162float(h0));
            bf16 l1 = __float2bfloat16(v.y - __bfloat162float(h1));
            bf16 l2 = __float2bfloat16(v.z - __bfloat162float(h2));
            bf16 l3 = __float2bfloat16(v.w - __bfloat162float(h3));
            bf162 hA; hA.x = h0; hA.y = h1;
            bf162 hB; hB.x = h2; hB.y = h3;
            bf162 lA; lA.x = l0; lA.y = l1;
            bf162 lB; lB.x = l2; lB.y = l3;
            *reinterpret_cast<bf162*>(Ch + go)     = hA;
            *reinterpret_cast<bf162*>(Ch + go + 2) = hB;
            *reinterpret_cast<bf162*>(Cl + go)     = lA;
            *reinterpret_cast<bf162*>(Cl + go + 2) = lB;
        } else {
            *reinterpret_cast<float4*>(Cf + go) = v;
        }
    }
}

// ---------------------------------------------------------------------------
// fp32 -> bf16 hi/lo split (no transpose), vectorized
// ---------------------------------------------------------------------------
__global__ void convert_split(const float4* __restrict__ src,
                              bf162* __restrict__ hi, bf162* __restrict__ lo, int n4)
{
    int i = blockIdx.x * blockDim.x + threadIdx.x;
    if (i >= n4) return;
    float4 v = src[i];
    bf16 h0 = __float2bfloat16(v.x), h1 = __float2bfloat16(v.y);
    bf16 h2 = __float2bfloat16(v.z), h3 = __float2bfloat16(v.w);
    bf16 l0 = __float2bfloat16(v.x - __bfloat162float(h0));
    bf16 l1 = __float2bfloat16(v.y - __bfloat162float(h1));
    bf16 l2 = __float2bfloat16(v.z - __bfloat162float(h2));
    bf16 l3 = __float2bfloat16(v.w - __bfloat162float(h3));
    bf162 a; a.x = h0; a.y = h1;
    bf162 b; b.x = h2; b.y = h3;
    bf162 c; c.x = l0; c.y = l1;
    bf162 e; e.x = l2; e.y = l3;
    hi[2 * i] = a; hi[2 * i + 1] = b;
    lo[2 * i] = c; lo[2 * i + 1] = e;
}

// ---------------------------------------------------------------------------
// W [K, N] fp32  ->  Wt hi/lo [N, K] bf16 (transpose + split)
// ---------------------------------------------------------------------------
__global__ void transpose_split(const float* __restrict__ W,
                                bf16* __restrict__ Th, bf16* __restrict__ Tl,
                                int K, int N)
{
    __shared__ float t[32][33];
    const int n0 = blockIdx.x * 32, k0 = blockIdx.y * 32;
    const int tx = threadIdx.x, ty = threadIdx.y;     // 32 x 8
#pragma unroll
    for (int r = 0; r < 32; r += 8)
        t[ty + r][tx] = W[(size_t)(k0 + ty + r) * N + n0 + tx];
    __syncthreads();
#pragma unroll
    for (int r = 0; r < 32; r += 8) {
        float v = t[tx][ty + r];
        bf16 h = __float2bfloat16(v);
        bf16 l = __float2bfloat16(v - __bfloat162float(h));
        size_t o = (size_t)(n0 + ty + r) * K + k0 + tx;
        Th[o] = h; Tl[o] = l;
    }
}

// ---------------------------------------------------------------------------
// softmax over 64-wide rows (one warp per row, 2 cols/lane)
// ---------------------------------------------------------------------------
__global__ void d2_softmax(const float* __restrict__ L, float* __restrict__ D2)
{
    const int row = (blockIdx.x * blockDim.x + threadIdx.x) >> 5;
    const int l = threadIdx.x & 31;
    float a = L[(size_t)row * SIZE + l];
    float b = L[(size_t)row * SIZE + l + 32];
    float m = fmaxf(a, b);
#pragma unroll
    for (int o = 16; o > 0; o >>= 1) m = fmaxf(m, __shfl_xor_sync(0xffffffffu, m, o));
    float ea = expf(a - m), eb = expf(b - m);
    float s = ea + eb;
#pragma unroll
    for (int o = 16; o > 0; o >>= 1) s += __shfl_xor_sync(0xffffffffu, s, o);
    float inv = 1.0f / s;
    D2[(size_t)row * SIZE + l]      = ea * inv;
    D2[(size_t)row * SIZE + l + 32] = eb * inv;
}

// ---------------------------------------------------------------------------
// Finalize: per row — softmax over 4096 logits, then out[y]=max_x min(p,d2)
// ---------------------------------------------------------------------------
__global__ __launch_bounds__(256) void finalize(
    const float* __restrict__ logits, const float* __restrict__ d2,
    float* __restrict__ out)
{
    __shared__ float sl[NN];
    __shared__ float sred[8];
    __shared__ float sd[SIZE];

    const int b = blockIdx.x, tid = threadIdx.x;
    const float4* lrow = (const float4*)(logits + (size_t)b * NN);

    float lm = -1e30f;
#pragma unroll
    for (int l = 0; l < 4; l++) {
        int j = tid + l * 256;
        float4 t = lrow[j];
        *(float4*)&sl[4 * j] = t;
        lm = fmaxf(lm, fmaxf(fmaxf(t.x, t.y), fmaxf(t.z, t.w)));
    }
#pragma unroll
    for (int o = 16; o > 0; o >>= 1) lm = fmaxf(lm, __shfl_xor_sync(0xffffffffu, lm, o));
    if ((tid & 31) == 0) sred[tid >> 5] = lm;
    __syncthreads();
    if (tid < 32) {
        float v2 = (tid < 8) ? sred[tid] : -1e30f;
#pragma unroll
        for (int o = 4; o > 0; o >>= 1) v2 = fmaxf(v2, __shfl_xor_sync(0xffffffffu, v2, o));
        if (tid == 0) sred[0] = v2;
    }
    __syncthreads();
    const float m = sred[0];
    __syncthreads();

    float ls = 0.f;
#pragma unroll
    for (int l = 0; l < 4; l++) {
        int j = tid + l * 256;
        float4 t = *(float4*)&sl[4 * j];
        t.x = expf(t.x - m); t.y = expf(t.y - m);
        t.z = expf(t.z - m); t.w = expf(t.w - m);
        *(float4*)&sl[4 * j] = t;
        ls += t.x + t.y + t.z + t.w;
    }
#pragma unroll
    for (int o = 16; o > 0; o >>= 1) ls += __shfl_xor_sync(0xffffffffu, ls, o);
    if ((tid & 31) == 0) sred[tid >> 5] = ls;
    __syncthreads();
    if (tid < 32) {
        float v2 = (tid < 8) ? sred[tid] : 0.f;
#pragma unroll
        for (int o = 4; o > 0; o >>= 1) v2 += __shfl_xor_sync(0xffffffffu, v2, o);
        if (tid == 0) sred[0] = v2;
    }
    if (tid < SIZE) sd[tid] = d2[(size_t)b * SIZE + tid];
    __syncthreads();
    const float inv = 1.0f / sred[0];

    if (tid < SIZE) {
        float best = -1e30f;
#pragma unroll 8
        for (int x = 0; x < SIZE; x++)
            best = fmaxf(best, fminf(sl[x * SIZE + tid] * inv, sd[x]));
        out[(size_t)b * SIZE + tid] = best;
    }
}

// ---------------------------------------------------------------------------
// Launch
// ---------------------------------------------------------------------------
extern "C" void kernel_launch(void* const* d_in, const int* in_sizes, int n_in,
                              void* d_out, int out_size)
{
    const float* x   = (const float*)d_in[0];
    const float* W1a = (const float*)d_in[1];
    const float* b1a = (const float*)d_in[2];
    const float* W2a = (const float*)d_in[3];
    const float* b2a = (const float*)d_in[4];
    const float* W1b = (const float*)d_in[5];
    const float* b1b = (const float*)d_in[6];
    const float* W2b = (const float*)d_in[7];
    const float* b2b = (const float*)d_in[8];
    float* out = (float*)d_out;

    bf16 *Xh, *Xl, *W1aTh, *W1aTl, *W1bTh, *W1bTl, *W2aTh, *W2aTl, *W2bTh, *W2bTl;
    bf16 *Hah, *Hal, *Hbh, *Hbl;
    float *Lg, *Dlog, *D2;
    cudaGetSymbolAddress((void**)&Xh, g_Xh);       cudaGetSymbolAddress((void**)&Xl, g_Xl);
    cudaGetSymbolAddress((void**)&W1aTh, g_W1aTh); cudaGetSymbolAddress((void**)&W1aTl, g_W1aTl);
    cudaGetSymbolAddress((void**)&W1bTh, g_W1bTh); cudaGetSymbolAddress((void**)&W1bTl, g_W1bTl);
    cudaGetSymbolAddress((void**)&W2aTh, g_W2aTh); cudaGetSymbolAddress((void**)&W2aTl, g_W2aTl);
    cudaGetSymbolAddress((void**)&W2bTh, g_W2bTh); cudaGetSymbolAddress((void**)&W2bTl, g_W2bTl);
    cudaGetSymbolAddress((void**)&Hah, g_Hah);     cudaGetSymbolAddress((void**)&Hal, g_Hal);
    cudaGetSymbolAddress((void**)&Hbh, g_Hbh);     cudaGetSymbolAddress((void**)&Hbl, g_Hbl);
    cudaGetSymbolAddress((void**)&Lg, g_Lg);
    cudaGetSymbolAddress((void**)&Dlog, g_Dlog);   cudaGetSymbolAddress((void**)&D2, g_D2);

    // dynamic smem: stage = 2*(128+BN)*40*2 bytes
    const int smem128 = 3 * 2 * (128 + 128) * 40 * 2;   // 122880
    const int smem64  = 3 * 2 * (128 + 64)  * 40 * 2;   // 92160
    cudaFuncSetAttribute((const void*)mma_gemm<128, true,  true >,
                         cudaFuncAttributeMaxDynamicSharedMemorySize, smem128);
    cudaFuncSetAttribute((const void*)mma_gemm<128, false, false>,
                         cudaFuncAttributeMaxDynamicSharedMemorySize, smem128);
    cudaFuncSetAttribute((const void*)mma_gemm<64,  false, false>,
                         cudaFuncAttributeMaxDynamicSharedMemorySize, smem64);

    convert_split<<<(BATCH * D_IN / 4 + 255) / 256, 256>>>(
        (const float4*)x, (bf162*)Xh, (bf162*)Xl, BATCH * D_IN / 4);

    transpose_split<<<dim3(D_IN / 32, D_IN / 32), dim3(32, 8)>>>(W1a, W1aTh, W1aTl, D_IN, D_IN);
    transpose_split<<<dim3(D_IN / 32, D_IN / 32), dim3(32, 8)>>>(W1b, W1bTh, W1bTl, D_IN, D_IN);
    transpose_split<<<dim3(NN   / 32, D_IN / 32), dim3(32, 8)>>>(W2a, W2aTh, W2aTl, D_IN, NN);
    transpose_split<<<dim3(SIZE / 32, D_IN / 32), dim3(32, 8)>>>(W2b, W2bTh, W2bTl, D_IN, SIZE);

    // layer 1 (both branches): relu, bf16 hi/lo outputs
    mma_gemm<128, true, true><<<dim3(D_IN / 128, BATCH / 128), 256, smem128>>>(
        Xh, Xl, W1aTh, W1aTl, b1a, nullptr, Hah, Hal, D_IN);
    mma_gemm<128, true, true><<<dim3(D_IN / 128, BATCH / 128), 256, smem128>>>(
        Xh, Xl, W1bTh, W1bTl, b1b, nullptr, Hbh, Hbl, D_IN);

    // layer 2a: logits [8192, 4096] fp32
    mma_gemm<128, false, false><<<dim3(NN / 128, BATCH / 128), 256, smem128>>>(
        Hah, Hal, W2aTh, W2aTl, b2a, Lg, nullptr, nullptr, NN);

    // layer 2b: d2 logits [8192, 64] fp32
    mma_gemm<64, false, false><<<dim3(1, BATCH / 128), 256, smem64>>>(
        Hbh, Hbl, W2bTh, W2bTl, b2b, Dlog, nullptr, nullptr, SIZE);

    d2_softmax<<<BATCH * 32 / 256, 256>>>(Dlog, D2);
    finalize<<<BATCH, 256>>>(Lg, D2, out);
}

// round 4
// speedup vs baseline: 3.4702x; 1.5514x over previous
#include <cuda_runtime.h>
#include <cuda_fp16.h>
#include <math.h>
#include <stdint.h>

#define BATCH 8192
#define D_IN  1024
#define SIZE  64
#define NN    4096

typedef __half  f16;

// ---------------------------------------------------------------------------
// Scratch (__device__ globals; no allocation allowed)
// ---------------------------------------------------------------------------
__device__ __align__(16) f16 g_Xh [(size_t)BATCH * D_IN];
__device__ __align__(16) f16 g_Xl [(size_t)BATCH * D_IN];
__device__ __align__(16) f16 g_W1aT[(size_t)D_IN * D_IN];
__device__ __align__(16) f16 g_W1bT[(size_t)D_IN * D_IN];
__device__ __align__(16) f16 g_W2aT[(size_t)NN * D_IN];
__device__ __align__(16) f16 g_W2bT[(size_t)SIZE * D_IN];
__device__ __align__(16) f16 g_Hah[(size_t)BATCH * D_IN];
__device__ __align__(16) f16 g_Hal[(size_t)BATCH * D_IN];
__device__ __align__(16) f16 g_Hbh[(size_t)BATCH * D_IN];
__device__ __align__(16) f16 g_Hbl[(size_t)BATCH * D_IN];
__device__ __align__(16) float g_Lg [(size_t)BATCH * NN];
__device__ __align__(16) float g_Dlog[(size_t)BATCH * SIZE];
__device__ __align__(16) float g_D2 [(size_t)BATCH * SIZE];

// ---------------------------------------------------------------------------
// PTX helpers (target-portable, sm_80+)
// ---------------------------------------------------------------------------
__device__ __forceinline__ uint32_t smem_u32(const void* p) {
    uint32_t a;
    asm("{ .reg .u64 t; cvta.to.shared.u64 t, %1; cvt.u32.u64 %0, t; }"
        : "=r"(a) : "l"(p));
    return a;
}

#define CP16(dst, src) \
    asm volatile("cp.async.cg.shared.global [%0], [%1], 16;" :: "r"(dst), "l"(src) : "memory")
#define CP_COMMIT() asm volatile("cp.async.commit_group;" ::: "memory")
#define CP_WAIT(n)  asm volatile("cp.async.wait_group %0;" :: "n"(n) : "memory")

#define LDSM4(r0, r1, r2, r3, a) \
    asm volatile("ldmatrix.sync.aligned.m8n8.x4.shared.b16 {%0,%1,%2,%3}, [%4];" \
                 : "=r"(r0), "=r"(r1), "=r"(r2), "=r"(r3) : "r"(a))

#define MMA16816(d, a, b) \
    asm volatile("mma.sync.aligned.m16n8k16.row.col.f32.f16.f16.f32 " \
                 "{%0,%1,%2,%3}, {%4,%5,%6,%7}, {%8,%9}, {%0,%1,%2,%3};" \
                 : "+f"((d)[0]), "+f"((d)[1]), "+f"((d)[2]), "+f"((d)[3]) \
                 : "r"((a)[0]), "r"((a)[1]), "r"((a)[2]), "r"((a)[3]), \
                   "r"((b)[0]), "r"((b)[1]))

// ---------------------------------------------------------------------------
// Split-fp16 MMA GEMM:  C[M, Ntot] = act((Ah+Al) @ B^T + bias)
// A: [M, 1024] K-major fp16 hi/lo.  B: [Ntot, 1024] K-major fp16 (single).
// CTA tile 128 x BN, BK=32, 3-stage cp.async pipeline, 256 threads.
// Warp grid 2(M) x 4(N): warp tile 64 x (BN/4).  2 MMA terms per pair.
// ---------------------------------------------------------------------------
template <int BN, bool RELU, bool OUTSPLIT>
__global__ __launch_bounds__(256, 2) void mma_gemm(
    const f16* __restrict__ Ahg, const f16* __restrict__ Alg,
    const f16* __restrict__ Bg,
    const float* __restrict__ bias,
    float* __restrict__ Cf, f16* __restrict__ Ch, f16* __restrict__ Cl,
    int Ntot)
{
    constexpr int BM = 128, S = 3;
    constexpr int NCHUNK = D_IN / 32;             // 32 k-chunks of 32
    constexpr int ROWP = 40;                      // f16/row: 32 data + 8 pad
    constexpr int AE = BM * ROWP;                 // f16 per A array
    constexpr int BE = BN * ROWP;
    constexpr int STAGE = 2 * AE + BE;            // f16 per stage
    constexpr int ACH = BM * 4;                   // 16B chunks per A array
    constexpr int BCH = BN * 4;
    constexpr int NCHK = 2 * ACH + BCH;           // chunks per stage
    constexpr int NFRAG = BN / 32;                // n-frags per warp (4 or 2)
    constexpr int WNT = BN / 4;                   // warp n-tile

    extern __shared__ __align__(16) f16 sm[];

    const int tid = threadIdx.x, lane = tid & 31, wid = tid >> 5;
    const int warp_m = wid & 1, warp_n = wid >> 1;
    const int m0 = blockIdx.y * BM, n0 = blockIdx.x * BN;
    const uint32_t sbase = smem_u32(sm);

    auto issue_stage = [&](int i) {
        const int k0 = i * 32;
        const uint32_t sb = sbase + (uint32_t)(i % S) * STAGE * 2;
#pragma unroll
        for (int p = 0; p < (NCHK + 255) / 256; p++) {
            int c = tid + p * 256;
            if (c < NCHK) {
                const f16* g;
                uint32_t soff;
                if (c < ACH) {
                    int r = c >> 2, kc = c & 3;
                    g = Ahg + (size_t)(m0 + r) * D_IN + k0 + kc * 8;
                    soff = (uint32_t)(r * ROWP + kc * 8);
                } else if (c < 2 * ACH) {
                    int cc = c - ACH, r = cc >> 2, kc = cc & 3;
                    g = Alg + (size_t)(m0 + r) * D_IN + k0 + kc * 8;
                    soff = (uint32_t)(AE + r * ROWP + kc * 8);
                } else {
                    int cc = c - 2 * ACH, r = cc >> 2, kc = cc & 3;
                    g = Bg + (size_t)(n0 + r) * D_IN + k0 + kc * 8;
                    soff = (uint32_t)(2 * AE + r * ROWP + kc * 8);
                }
                CP16(sb + soff * 2, (const char*)g);
            }
        }
    };

    float acc[4][NFRAG][4];
#pragma unroll
    for (int f = 0; f < 4; f++)
#pragma unroll
        for (int n = 0; n < NFRAG; n++)
#pragma unroll
            for (int q = 0; q < 4; q++) acc[f][n][q] = 0.f;

    const int aRow = warp_m * 64 + (lane & 15);
    const int aKl  = (lane >> 4) << 3;
    const int bRow = warp_n * WNT + (lane & 7) + ((lane >> 4) << 3);
    const int bKl  = ((lane >> 3) & 1) << 3;

#pragma unroll
    for (int i = 0; i < S - 1; i++) { issue_stage(i); CP_COMMIT(); }

    for (int i = 0; i < NCHUNK; i++) {
        CP_WAIT(S - 2);
        __syncthreads();

        if (i + S - 1 < NCHUNK) issue_stage(i + S - 1);
        CP_COMMIT();

        const uint32_t sb = sbase + (uint32_t)(i % S) * STAGE * 2;
#pragma unroll
        for (int k16 = 0; k16 < 32; k16 += 16) {
            uint32_t bh[NFRAG][2];
#pragma unroll
            for (int p = 0; p < NFRAG / 2; p++) {
                uint32_t rb = sb + (uint32_t)(2 * AE + (bRow + p * 16) * ROWP + k16 + bKl) * 2;
                LDSM4(bh[2 * p][0], bh[2 * p][1], bh[2 * p + 1][0], bh[2 * p + 1][1], rb);
            }
#pragma unroll
            for (int f = 0; f < 4; f++) {
                uint32_t ah[4], al[4];
                uint32_t ra = sb + (uint32_t)(((aRow + f * 16) * ROWP) + k16 + aKl) * 2;
                LDSM4(ah[0], ah[1], ah[2], ah[3], ra);
                LDSM4(al[0], al[1], al[2], al[3], ra + AE * 2);
#pragma unroll
                for (int n = 0; n < NFRAG; n++) {
                    MMA16816(acc[f][n], ah, bh[n]);
                    MMA16816(acc[f][n], al, bh[n]);
                }
            }
        }
    }

    // ---- epilogue: stage C through smem for coalesced stores ----
    __syncthreads();
    constexpr int P = BN + 4;
    float* smC = reinterpret_cast<float*>(sm);
#pragma unroll
    for (int f = 0; f < 4; f++)
#pragma unroll
        for (int n = 0; n < NFRAG; n++) {
            int r = warp_m * 64 + f * 16 + (lane >> 2);
            int c = warp_n * WNT + n * 8 + 2 * (lane & 3);
            *reinterpret_cast<float2*>(&smC[r * P + c]) =
                make_float2(acc[f][n][0], acc[f][n][1]);
            *reinterpret_cast<float2*>(&smC[(r + 8) * P + c]) =
                make_float2(acc[f][n][2], acc[f][n][3]);
        }
    __syncthreads();

    constexpr int C4 = BN / 4;
#pragma unroll
    for (int u = 0; u < BM * C4 / 256; u++) {
        int idx = tid + u * 256;
        int r = idx / C4, c4 = idx % C4;
        float4 v = *reinterpret_cast<float4*>(&smC[r * P + c4 * 4]);
        int col = n0 + c4 * 4;
        v.x += bias[col]; v.y += bias[col + 1]; v.z += bias[col + 2]; v.w += bias[col + 3];
        if (RELU) {
            v.x = fmaxf(v.x, 0.f); v.y = fmaxf(v.y, 0.f);
            v.z = fmaxf(v.z, 0.f); v.w = fmaxf(v.w, 0.f);
        }
        size_t go = (size_t)(m0 + r) * Ntot + col;
        if (OUTSPLIT) {
            f16 h0 = __float2half(v.x), h1 = __float2half(v.y);
            f16 h2 = __float2half(v.z), h3 = __float2half(v.w);
            f16 l0 = __float2half(v.x - __half2float(h0));
            f16 l1 = __float2half(v.y - __half2float(h1));
            f16 l2 = __float2half(v.z - __half2float(h2));
            f16 l3 = __float2half(v.w - __half2float(h3));
            __half2 hA = __halves2half2(h0, h1), hB = __halves2half2(h2, h3);
            __half2 lA = __halves2half2(l0, l1), lB = __halves2half2(l2, l3);
            *reinterpret_cast<__half2*>(Ch + go)     = hA;
            *reinterpret_cast<__half2*>(Ch + go + 2) = hB;
            *reinterpret_cast<__half2*>(Cl + go)     = lA;
            *reinterpret_cast<__half2*>(Cl + go + 2) = lB;
        } else {
            *reinterpret_cast<float4*>(Cf + go) = v;
        }
    }
}

// ---------------------------------------------------------------------------
// fp32 -> fp16 hi/lo split (no transpose), vectorized
// ---------------------------------------------------------------------------
__global__ void convert_split(const float4* __restrict__ src,
                              __half2* __restrict__ hi, __half2* __restrict__ lo, int n4)
{
    int i = blockIdx.x * blockDim.x + threadIdx.x;
    if (i >= n4) return;
    float4 v = src[i];
    f16 h0 = __float2half(v.x), h1 = __float2half(v.y);
    f16 h2 = __float2half(v.z), h3 = __float2half(v.w);
    f16 l0 = __float2half(v.x - __half2float(h0));
    f16 l1 = __float2half(v.y - __half2float(h1));
    f16 l2 = __float2half(v.z - __half2float(h2));
    f16 l3 = __float2half(v.w - __half2float(h3));
    hi[2 * i]     = __halves2half2(h0, h1);
    hi[2 * i + 1] = __halves2half2(h2, h3);
    lo[2 * i]     = __halves2half2(l0, l1);
    lo[2 * i + 1] = __halves2half2(l2, l3);
}

// ---------------------------------------------------------------------------
// W [K, N] fp32  ->  Wt [N, K] fp16 (transpose + round)
// ---------------------------------------------------------------------------
__global__ void transpose_cvt(const float* __restrict__ W,
                              f16* __restrict__ T, int K, int N)
{
    __shared__ float t[32][33];
    const int n0 = blockIdx.x * 32, k0 = blockIdx.y * 32;
    const int tx = threadIdx.x, ty = threadIdx.y;     // 32 x 8
#pragma unroll
    for (int r = 0; r < 32; r += 8)
        t[ty + r][tx] = W[(size_t)(k0 + ty + r) * N + n0 + tx];
    __syncthreads();
#pragma unroll
    for (int r = 0; r < 32; r += 8) {
        size_t o = (size_t)(n0 + ty + r) * K + k0 + tx;
        T[o] = __float2half(t[tx][ty + r]);
    }
}

// ---------------------------------------------------------------------------
// softmax over 64-wide rows (one warp per row, 2 cols/lane)
// ---------------------------------------------------------------------------
__global__ void d2_softmax(const float* __restrict__ L, float* __restrict__ D2)
{
    const int row = (blockIdx.x * blockDim.x + threadIdx.x) >> 5;
    const int l = threadIdx.x & 31;
    float a = L[(size_t)row * SIZE + l];
    float b = L[(size_t)row * SIZE + l + 32];
    float m = fmaxf(a, b);
#pragma unroll
    for (int o = 16; o > 0; o >>= 1) m = fmaxf(m, __shfl_xor_sync(0xffffffffu, m, o));
    float ea = expf(a - m), eb = expf(b - m);
    float s = ea + eb;
#pragma unroll
    for (int o = 16; o > 0; o >>= 1) s += __shfl_xor_sync(0xffffffffu, s, o);
    float inv = 1.0f / s;
    D2[(size_t)row * SIZE + l]      = ea * inv;
    D2[(size_t)row * SIZE + l + 32] = eb * inv;
}

// ---------------------------------------------------------------------------
// Finalize: per row — softmax over 4096 logits, then out[y]=max_x min(p,d2)
// ---------------------------------------------------------------------------
__global__ __launch_bounds__(256) void finalize(
    const float* __restrict__ logits, const float* __restrict__ d2,
    float* __restrict__ out)
{
    __shared__ float sl[NN];
    __shared__ float sred[8];
    __shared__ float sd[SIZE];

    const int b = blockIdx.x, tid = threadIdx.x;
    const float4* lrow = (const float4*)(logits + (size_t)b * NN);

    float lm = -1e30f;
#pragma unroll
    for (int l = 0; l < 4; l++) {
        int j = tid + l * 256;
        float4 t = lrow[j];
        *(float4*)&sl[4 * j] = t;
        lm = fmaxf(lm, fmaxf(fmaxf(t.x, t.y), fmaxf(t.z, t.w)));
    }
#pragma unroll
    for (int o = 16; o > 0; o >>= 1) lm = fmaxf(lm, __shfl_xor_sync(0xffffffffu, lm, o));
    if ((tid & 31) == 0) sred[tid >> 5] = lm;
    __syncthreads();
    if (tid < 32) {
        float v2 = (tid < 8) ? sred[tid] : -1e30f;
#pragma unroll
        for (int o = 4; o > 0; o >>= 1) v2 = fmaxf(v2, __shfl_xor_sync(0xffffffffu, v2, o));
        if (tid == 0) sred[0] = v2;
    }
    __syncthreads();
    const float m = sred[0];
    __syncthreads();

    float ls = 0.f;
#pragma unroll
    for (int l = 0; l < 4; l++) {
        int j = tid + l * 256;
        float4 t = *(float4*)&sl[4 * j];
        t.x = expf(t.x - m); t.y = expf(t.y - m);
        t.z = expf(t.z - m); t.w = expf(t.w - m);
        *(float4*)&sl[4 * j] = t;
        ls += t.x + t.y + t.z + t.w;
    }
#pragma unroll
    for (int o = 16; o > 0; o >>= 1) ls += __shfl_xor_sync(0xffffffffu, ls, o);
    if ((tid & 31) == 0) sred[tid >> 5] = ls;
    __syncthreads();
    if (tid < 32) {
        float v2 = (tid < 8) ? sred[tid] : 0.f;
#pragma unroll
        for (int o = 4; o > 0; o >>= 1) v2 += __shfl_xor_sync(0xffffffffu, v2, o);
        if (tid == 0) sred[0] = v2;
    }
    if (tid < SIZE) sd[tid] = d2[(size_t)b * SIZE + tid];
    __syncthreads();
    const float inv = 1.0f / sred[0];

    if (tid < SIZE) {
        float best = -1e30f;
#pragma unroll 8
        for (int x = 0; x < SIZE; x++)
            best = fmaxf(best, fminf(sl[x * SIZE + tid] * inv, sd[x]));
        out[(size_t)b * SIZE + tid] = best;
    }
}

// ---------------------------------------------------------------------------
// Launch
// ---------------------------------------------------------------------------
extern "C" void kernel_launch(void* const* d_in, const int* in_sizes, int n_in,
                              void* d_out, int out_size)
{
    const float* x   = (const float*)d_in[0];
    const float* W1a = (const float*)d_in[1];
    const float* b1a = (const float*)d_in[2];
    const float* W2a = (const float*)d_in[3];
    const float* b2a = (const float*)d_in[4];
    const float* W1b = (const float*)d_in[5];
    const float* b1b = (const float*)d_in[6];
    const float* W2b = (const float*)d_in[7];
    const float* b2b = (const float*)d_in[8];
    float* out = (float*)d_out;

    f16 *Xh, *Xl, *W1aT, *W1bT, *W2aT, *W2bT, *Hah, *Hal, *Hbh, *Hbl;
    float *Lg, *Dlog, *D2;
    cudaGetSymbolAddress((void**)&Xh, g_Xh);     cudaGetSymbolAddress((void**)&Xl, g_Xl);
    cudaGetSymbolAddress((void**)&W1aT, g_W1aT); cudaGetSymbolAddress((void**)&W1bT, g_W1bT);
    cudaGetSymbolAddress((void**)&W2aT, g_W2aT); cudaGetSymbolAddress((void**)&W2bT, g_W2bT);
    cudaGetSymbolAddress((void**)&Hah, g_Hah);   cudaGetSymbolAddress((void**)&Hal, g_Hal);
    cudaGetSymbolAddress((void**)&Hbh, g_Hbh);   cudaGetSymbolAddress((void**)&Hbl, g_Hbl);
    cudaGetSymbolAddress((void**)&Lg, g_Lg);
    cudaGetSymbolAddress((void**)&Dlog, g_Dlog); cudaGetSymbolAddress((void**)&D2, g_D2);

    // dynamic smem: stage = (2*128 + BN)*40*2 bytes, 3 stages
    const int smem128 = 3 * (2 * 128 + 128) * 40 * 2;   // 92160
    const int smem64  = 3 * (2 * 128 + 64)  * 40 * 2;   // 76800
    cudaFuncSetAttribute((const void*)mma_gemm<128, true,  true >,
                         cudaFuncAttributeMaxDynamicSharedMemorySize, smem128);
    cudaFuncSetAttribute((const void*)mma_gemm<128, false, false>,
                         cudaFuncAttributeMaxDynamicSharedMemorySize, smem128);
    cudaFuncSetAttribute((const void*)mma_gemm<64,  false, false>,
                         cudaFuncAttributeMaxDynamicSharedMemorySize, smem64);

    convert_split<<<(BATCH * D_IN / 4 + 255) / 256, 256>>>(
        (const float4*)x, (__half2*)Xh, (__half2*)Xl, BATCH * D_IN / 4);

    transpose_cvt<<<dim3(D_IN / 32, D_IN / 32), dim3(32, 8)>>>(W1a, W1aT, D_IN, D_IN);
    transpose_cvt<<<dim3(D_IN / 32, D_IN / 32), dim3(32, 8)>>>(W1b, W1bT, D_IN, D_IN);
    transpose_cvt<<<dim3(NN   / 32, D_IN / 32), dim3(32, 8)>>>(W2a, W2aT, D_IN, NN);
    transpose_cvt<<<dim3(SIZE / 32, D_IN / 32), dim3(32, 8)>>>(W2b, W2bT, D_IN, SIZE);

    // layer 1 (both branches): relu, fp16 hi/lo outputs
    mma_gemm<128, true, true><<<dim3(D_IN / 128, BATCH / 128), 256, smem128>>>(
        Xh, Xl, W1aT, b1a, nullptr, Hah, Hal, D_IN);
    mma_gemm<128, true, true><<<dim3(D_IN / 128, BATCH / 128), 256, smem128>>>(
        Xh, Xl, W1bT, b1b, nullptr, Hbh, Hbl, D_IN);

    // layer 2a: logits [8192, 4096] fp32
    mma_gemm<128, false, false><<<dim3(NN / 128, BATCH / 128), 256, smem128>>>(
        Hah, Hal, W2aT, b2a, Lg, nullptr, nullptr, NN);

    // layer 2b: d2 logits [8192, 64] fp32
    mma_gemm<64, false, false><<<dim3(1, BATCH / 128), 256, smem64>>>(
        Hbh, Hbl, W2bT, b2b, Dlog, nullptr, nullptr, SIZE);

    d2_softmax<<<BATCH * 32 / 256, 256>>>(Dlog, D2);
    finalize<<<BATCH, 256>>>(Lg, D2, out);
}

// round 5
// speedup vs baseline: 5.4338x; 1.5659x over previous
#include <cuda_runtime.h>
#include <cuda_fp16.h>
#include <math.h>
#include <stdint.h>

#define BATCH 8192
#define D_IN  1024
#define SIZE  64
#define NN    4096

typedef __half  f16;

// ---------------------------------------------------------------------------
// Scratch (__device__ globals; no allocation allowed)
// ---------------------------------------------------------------------------
__device__ __align__(16) f16 g_X  [(size_t)BATCH * D_IN];
__device__ __align__(16) f16 g_W1aT[(size_t)D_IN * D_IN];
__device__ __align__(16) f16 g_W1bT[(size_t)D_IN * D_IN];
__device__ __align__(16) f16 g_W2aT[(size_t)NN * D_IN];
__device__ __align__(16) f16 g_W2bT[(size_t)SIZE * D_IN];
__device__ __align__(16) f16 g_Ha [(size_t)BATCH * D_IN];
__device__ __align__(16) f16 g_Hb [(size_t)BATCH * D_IN];
__device__ __align__(16) float g_Lg [(size_t)BATCH * NN];
__device__ __align__(16) float g_Dlog[(size_t)BATCH * SIZE];
__device__ __align__(16) float g_D2 [(size_t)BATCH * SIZE];

// ---------------------------------------------------------------------------
// PTX helpers (target-portable, sm_80+)
// ---------------------------------------------------------------------------
__device__ __forceinline__ uint32_t smem_u32(const void* p) {
    uint32_t a;
    asm("{ .reg .u64 t; cvta.to.shared.u64 t, %1; cvt.u32.u64 %0, t; }"
        : "=r"(a) : "l"(p));
    return a;
}

#define CP16(dst, src) \
    asm volatile("cp.async.cg.shared.global [%0], [%1], 16;" :: "r"(dst), "l"(src) : "memory")
#define CP_COMMIT() asm volatile("cp.async.commit_group;" ::: "memory")
#define CP_WAIT(n)  asm volatile("cp.async.wait_group %0;" :: "n"(n) : "memory")

#define LDSM4(r0, r1, r2, r3, a) \
    asm volatile("ldmatrix.sync.aligned.m8n8.x4.shared.b16 {%0,%1,%2,%3}, [%4];" \
                 : "=r"(r0), "=r"(r1), "=r"(r2), "=r"(r3) : "r"(a))

#define MMA16816(d, a, b) \
    asm volatile("mma.sync.aligned.m16n8k16.row.col.f32.f16.f16.f32 " \
                 "{%0,%1,%2,%3}, {%4,%5,%6,%7}, {%8,%9}, {%0,%1,%2,%3};" \
                 : "+f"((d)[0]), "+f"((d)[1]), "+f"((d)[2]), "+f"((d)[3]) \
                 : "r"((a)[0]), "r"((a)[1]), "r"((a)[2]), "r"((a)[3]), \
                   "r"((b)[0]), "r"((b)[1]))

// ---------------------------------------------------------------------------
// fp16 HGEMM:  C[M, Ntot] = act(A @ B^T + bias)
// A: [M, 1024] K-major fp16.  B: [Ntot, 1024] K-major fp16.
// CTA tile 128 x BN, BK=32, 4-stage cp.async pipeline, 256 threads.
// Warp grid 2(M) x 4(N): warp tile 64 x (BN/4).
// ---------------------------------------------------------------------------
template <int BN, bool RELU, bool OUTF16>
__global__ __launch_bounds__(256, 2) void mma_gemm(
    const f16* __restrict__ Ag, const f16* __restrict__ Bg,
    const float* __restrict__ bias,
    float* __restrict__ Cf, f16* __restrict__ Ch,
    int Ntot)
{
    constexpr int BM = 128, S = 4;
    constexpr int NCHUNK = D_IN / 32;             // 32 k-chunks of 32
    constexpr int ROWP = 40;                      // f16/row: 32 data + 8 pad
    constexpr int AE = BM * ROWP;                 // f16 in A tile
    constexpr int BE = BN * ROWP;
    constexpr int STAGE = AE + BE;                // f16 per stage
    constexpr int ACH = BM * 4;                   // 16B chunks in A tile
    constexpr int BCH = BN * 4;
    constexpr int NCHK = ACH + BCH;               // chunks per stage
    constexpr int NFRAG = BN / 32;                // n-frags per warp (4 or 2)
    constexpr int WNT = BN / 4;                   // warp n-tile

    extern __shared__ __align__(16) f16 sm[];

    const int tid = threadIdx.x, lane = tid & 31, wid = tid >> 5;
    const int warp_m = wid & 1, warp_n = wid >> 1;
    const int m0 = blockIdx.y * BM, n0 = blockIdx.x * BN;
    const uint32_t sbase = smem_u32(sm);

    auto issue_stage = [&](int i) {
        const int k0 = i * 32;
        const uint32_t sb = sbase + (uint32_t)(i % S) * STAGE * 2;
#pragma unroll
        for (int p = 0; p < (NCHK + 255) / 256; p++) {
            int c = tid + p * 256;
            if (c < NCHK) {
                const f16* g;
                uint32_t soff;
                if (c < ACH) {
                    int r = c >> 2, kc = c & 3;
                    g = Ag + (size_t)(m0 + r) * D_IN + k0 + kc * 8;
                    soff = (uint32_t)(r * ROWP + kc * 8);
                } else {
                    int cc = c - ACH, r = cc >> 2, kc = cc & 3;
                    g = Bg + (size_t)(n0 + r) * D_IN + k0 + kc * 8;
                    soff = (uint32_t)(AE + r * ROWP + kc * 8);
                }
                CP16(sb + soff * 2, (const char*)g);
            }
        }
    };

    float acc[4][NFRAG][4];
#pragma unroll
    for (int f = 0; f < 4; f++)
#pragma unroll
        for (int n = 0; n < NFRAG; n++)
#pragma unroll
            for (int q = 0; q < 4; q++) acc[f][n][q] = 0.f;

    const int aRow = warp_m * 64 + (lane & 15);
    const int aKl  = (lane >> 4) << 3;
    const int bRow = warp_n * WNT + (lane & 7) + ((lane >> 4) << 3);
    const int bKl  = ((lane >> 3) & 1) << 3;

#pragma unroll
    for (int i = 0; i < S - 1; i++) { issue_stage(i); CP_COMMIT(); }

    for (int i = 0; i < NCHUNK; i++) {
        CP_WAIT(S - 2);
        __syncthreads();

        if (i + S - 1 < NCHUNK) issue_stage(i + S - 1);
        CP_COMMIT();

        const uint32_t sb = sbase + (uint32_t)(i % S) * STAGE * 2;
#pragma unroll
        for (int k16 = 0; k16 < 32; k16 += 16) {
            uint32_t bh[NFRAG][2];
#pragma unroll
            for (int p = 0; p < NFRAG / 2; p++) {
                uint32_t rb = sb + (uint32_t)(AE + (bRow + p * 16) * ROWP + k16 + bKl) * 2;
                LDSM4(bh[2 * p][0], bh[2 * p][1], bh[2 * p + 1][0], bh[2 * p + 1][1], rb);
            }
#pragma unroll
            for (int f = 0; f < 4; f++) {
                uint32_t ah[4];
                uint32_t ra = sb + (uint32_t)(((aRow + f * 16) * ROWP) + k16 + aKl) * 2;
                LDSM4(ah[0], ah[1], ah[2], ah[3], ra);
#pragma unroll
                for (int n = 0; n < NFRAG; n++)
                    MMA16816(acc[f][n], ah, bh[n]);
            }
        }
    }

    // ---- epilogue: stage C through smem for coalesced stores ----
    __syncthreads();
    constexpr int P = BN + 4;
    float* smC = reinterpret_cast<float*>(sm);
#pragma unroll
    for (int f = 0; f < 4; f++)
#pragma unroll
        for (int n = 0; n < NFRAG; n++) {
            int r = warp_m * 64 + f * 16 + (lane >> 2);
            int c = warp_n * WNT + n * 8 + 2 * (lane & 3);
            *reinterpret_cast<float2*>(&smC[r * P + c]) =
                make_float2(acc[f][n][0], acc[f][n][1]);
            *reinterpret_cast<float2*>(&smC[(r + 8) * P + c]) =
                make_float2(acc[f][n][2], acc[f][n][3]);
        }
    __syncthreads();

    constexpr int C4 = BN / 4;
#pragma unroll
    for (int u = 0; u < BM * C4 / 256; u++) {
        int idx = tid + u * 256;
        int r = idx / C4, c4 = idx % C4;
        float4 v = *reinterpret_cast<float4*>(&smC[r * P + c4 * 4]);
        int col = n0 + c4 * 4;
        v.x += bias[col]; v.y += bias[col + 1]; v.z += bias[col + 2]; v.w += bias[col + 3];
        if (RELU) {
            v.x = fmaxf(v.x, 0.f); v.y = fmaxf(v.y, 0.f);
            v.z = fmaxf(v.z, 0.f); v.w = fmaxf(v.w, 0.f);
        }
        size_t go = (size_t)(m0 + r) * Ntot + col;
        if (OUTF16) {
            __half2 a = __halves2half2(__float2half(v.x), __float2half(v.y));
            __half2 b = __halves2half2(__float2half(v.z), __float2half(v.w));
            *reinterpret_cast<__half2*>(Ch + go)     = a;
            *reinterpret_cast<__half2*>(Ch + go + 2) = b;
        } else {
            *reinterpret_cast<float4*>(Cf + go) = v;
        }
    }
}

// ---------------------------------------------------------------------------
// fp32 -> fp16 convert (vectorized)
// ---------------------------------------------------------------------------
__global__ void convert_f16(const float4* __restrict__ src,
                            __half2* __restrict__ dst, int n4)
{
    int i = blockIdx.x * blockDim.x + threadIdx.x;
    if (i >= n4) return;
    float4 v = src[i];
    dst[2 * i]     = __halves2half2(__float2half(v.x), __float2half(v.y));
    dst[2 * i + 1] = __halves2half2(__float2half(v.z), __float2half(v.w));
}

// ---------------------------------------------------------------------------
// W [K, N] fp32  ->  Wt [N, K] fp16 (transpose + round)
// ---------------------------------------------------------------------------
__global__ void transpose_cvt(const float* __restrict__ W,
                              f16* __restrict__ T, int K, int N)
{
    __shared__ float t[32][33];
    const int n0 = blockIdx.x * 32, k0 = blockIdx.y * 32;
    const int tx = threadIdx.x, ty = threadIdx.y;     // 32 x 8
#pragma unroll
    for (int r = 0; r < 32; r += 8)
        t[ty + r][tx] = W[(size_t)(k0 + ty + r) * N + n0 + tx];
    __syncthreads();
#pragma unroll
    for (int r = 0; r < 32; r += 8) {
        size_t o = (size_t)(n0 + ty + r) * K + k0 + tx;
        T[o] = __float2half(t[tx][ty + r]);
    }
}

// ---------------------------------------------------------------------------
// softmax over 64-wide rows (one warp per row, 2 cols/lane)
// ---------------------------------------------------------------------------
__global__ void d2_softmax(const float* __restrict__ L, float* __restrict__ D2)
{
    const int row = (blockIdx.x * blockDim.x + threadIdx.x) >> 5;
    const int l = threadIdx.x & 31;
    float a = L[(size_t)row * SIZE + l];
    float b = L[(size_t)row * SIZE + l + 32];
    float m = fmaxf(a, b);
#pragma unroll
    for (int o = 16; o > 0; o >>= 1) m = fmaxf(m, __shfl_xor_sync(0xffffffffu, m, o));
    float ea = expf(a - m), eb = expf(b - m);
    float s = ea + eb;
#pragma unroll
    for (int o = 16; o > 0; o >>= 1) s += __shfl_xor_sync(0xffffffffu, s, o);
    float inv = 1.0f / s;
    D2[(size_t)row * SIZE + l]      = ea * inv;
    D2[(size_t)row * SIZE + l + 32] = eb * inv;
}

// ---------------------------------------------------------------------------
// Finalize: per row — softmax over 4096 logits, then out[y]=max_x min(p,d2)
// ---------------------------------------------------------------------------
__global__ __launch_bounds__(256) void finalize(
    const float* __restrict__ logits, const float* __restrict__ d2,
    float* __restrict__ out)
{
    __shared__ float sl[NN];
    __shared__ float sred[8];
    __shared__ float sd[SIZE];

    const int b = blockIdx.x, tid = threadIdx.x;
    const float4* lrow = (const float4*)(logits + (size_t)b * NN);

    float lm = -1e30f;
#pragma unroll
    for (int l = 0; l < 4; l++) {
        int j = tid + l * 256;
        float4 t = lrow[j];
        *(float4*)&sl[4 * j] = t;
        lm = fmaxf(lm, fmaxf(fmaxf(t.x, t.y), fmaxf(t.z, t.w)));
    }
#pragma unroll
    for (int o = 16; o > 0; o >>= 1) lm = fmaxf(lm, __shfl_xor_sync(0xffffffffu, lm, o));
    if ((tid & 31) == 0) sred[tid >> 5] = lm;
    __syncthreads();
    if (tid < 32) {
        float v2 = (tid < 8) ? sred[tid] : -1e30f;
#pragma unroll
        for (int o = 4; o > 0; o >>= 1) v2 = fmaxf(v2, __shfl_xor_sync(0xffffffffu, v2, o));
        if (tid == 0) sred[0] = v2;
    }
    __syncthreads();
    const float m = sred[0];
    __syncthreads();

    float ls = 0.f;
#pragma unroll
    for (int l = 0; l < 4; l++) {
        int j = tid + l * 256;
        float4 t = *(float4*)&sl[4 * j];
        t.x = expf(t.x - m); t.y = expf(t.y - m);
        t.z = expf(t.z - m); t.w = expf(t.w - m);
        *(float4*)&sl[4 * j] = t;
        ls += t.x + t.y + t.z + t.w;
    }
#pragma unroll
    for (int o = 16; o > 0; o >>= 1) ls += __shfl_xor_sync(0xffffffffu, ls, o);
    if ((tid & 31) == 0) sred[tid >> 5] = ls;
    __syncthreads();
    if (tid < 32) {
        float v2 = (tid < 8) ? sred[tid] : 0.f;
#pragma unroll
        for (int o = 4; o > 0; o >>= 1) v2 += __shfl_xor_sync(0xffffffffu, v2, o);
        if (tid == 0) sred[0] = v2;
    }
    if (tid < SIZE) sd[tid] = d2[(size_t)b * SIZE + tid];
    __syncthreads();
    const float inv = 1.0f / sred[0];

    if (tid < SIZE) {
        float best = -1e30f;
#pragma unroll 8
        for (int x = 0; x < SIZE; x++)
            best = fmaxf(best, fminf(sl[x * SIZE + tid] * inv, sd[x]));
        out[(size_t)b * SIZE + tid] = best;
    }
}

// ---------------------------------------------------------------------------
// Launch
// ---------------------------------------------------------------------------
extern "C" void kernel_launch(void* const* d_in, const int* in_sizes, int n_in,
                              void* d_out, int out_size)
{
    const float* x   = (const float*)d_in[0];
    const float* W1a = (const float*)d_in[1];
    const float* b1a = (const float*)d_in[2];
    const float* W2a = (const float*)d_in[3];
    const float* b2a = (const float*)d_in[4];
    const float* W1b = (const float*)d_in[5];
    const float* b1b = (const float*)d_in[6];
    const float* W2b = (const float*)d_in[7];
    const float* b2b = (const float*)d_in[8];
    float* out = (float*)d_out;

    f16 *X, *W1aT, *W1bT, *W2aT, *W2bT, *Ha, *Hb;
    float *Lg, *Dlog, *D2;
    cudaGetSymbolAddress((void**)&X, g_X);
    cudaGetSymbolAddress((void**)&W1aT, g_W1aT); cudaGetSymbolAddress((void**)&W1bT, g_W1bT);
    cudaGetSymbolAddress((void**)&W2aT, g_W2aT); cudaGetSymbolAddress((void**)&W2bT, g_W2bT);
    cudaGetSymbolAddress((void**)&Ha, g_Ha);     cudaGetSymbolAddress((void**)&Hb, g_Hb);
    cudaGetSymbolAddress((void**)&Lg, g_Lg);
    cudaGetSymbolAddress((void**)&Dlog, g_Dlog); cudaGetSymbolAddress((void**)&D2, g_D2);

    // dynamic smem: 4 stages of (128+BN)*40*2 bytes; epilogue needs 128*(BN+4)*4
    const int smem128 = 81920;   // max(4*20480, 128*132*4=67584)
    const int smem64  = 61440;   // max(4*15360, 128*68*4=34816)
    cudaFuncSetAttribute((const void*)mma_gemm<128, true,  true >,
                         cudaFuncAttributeMaxDynamicSharedMemorySize, smem128);
    cudaFuncSetAttribute((const void*)mma_gemm<128, false, false>,
                         cudaFuncAttributeMaxDynamicSharedMemorySize, smem128);
    cudaFuncSetAttribute((const void*)mma_gemm<64,  false, false>,
                         cudaFuncAttributeMaxDynamicSharedMemorySize, smem64);

    convert_f16<<<(BATCH * D_IN / 4 + 255) / 256, 256>>>(
        (const float4*)x, (__half2*)X, BATCH * D_IN / 4);

    transpose_cvt<<<dim3(D_IN / 32, D_IN / 32), dim3(32, 8)>>>(W1a, W1aT, D_IN, D_IN);
    transpose_cvt<<<dim3(D_IN / 32, D_IN / 32), dim3(32, 8)>>>(W1b, W1bT, D_IN, D_IN);
    transpose_cvt<<<dim3(NN   / 32, D_IN / 32), dim3(32, 8)>>>(W2a, W2aT, D_IN, NN);
    transpose_cvt<<<dim3(SIZE / 32, D_IN / 32), dim3(32, 8)>>>(W2b, W2bT, D_IN, SIZE);

    // layer 1 (both branches): relu, fp16 outputs
    mma_gemm<128, true, true><<<dim3(D_IN / 128, BATCH / 128), 256, smem128>>>(
        X, W1aT, b1a, nullptr, Ha, D_IN);
    mma_gemm<128, true, true><<<dim3(D_IN / 128, BATCH / 128), 256, smem128>>>(
        X, W1bT, b1b, nullptr, Hb, D_IN);

    // layer 2a: logits [8192, 4096] fp32
    mma_gemm<128, false, false><<<dim3(NN / 128, BATCH / 128), 256, smem128>>>(
        Ha, W2aT, b2a, Lg, nullptr, NN);

    // layer 2b: d2 logits [8192, 64] fp32
    mma_gemm<64, false, false><<<dim3(1, BATCH / 128), 256, smem64>>>(
        Hb, W2bT, b2b, Dlog, nullptr, SIZE);

    d2_softmax<<<BATCH * 32 / 256, 256>>>(Dlog, D2);
    finalize<<<BATCH, 256>>>(Lg, D2, out);
}

// round 6
// speedup vs baseline: 5.4345x; 1.0001x over previous
#include <cuda_runtime.h>
#include <cuda_fp16.h>
#include <math.h>
#include <stdint.h>

#define BATCH 8192
#define D_IN  1024
#define SIZE  64
#define NN    4096

typedef __half  f16;

// ---------------------------------------------------------------------------
// Scratch (__device__ globals; no allocation allowed)
// ---------------------------------------------------------------------------
__device__ __align__(16) f16 g_X  [(size_t)BATCH * D_IN];
__device__ __align__(16) f16 g_W1aT[(size_t)D_IN * D_IN];
__device__ __align__(16) f16 g_W1bT[(size_t)D_IN * D_IN];
__device__ __align__(16) f16 g_W2aT[(size_t)NN * D_IN];
__device__ __align__(16) f16 g_W2bT[(size_t)SIZE * D_IN];
__device__ __align__(16) f16 g_Ha [(size_t)BATCH * D_IN];
__device__ __align__(16) f16 g_Hb [(size_t)BATCH * D_IN];
__device__ __align__(16) float g_Lg [(size_t)BATCH * NN];
__device__ __align__(16) float g_Dlog[(size_t)BATCH * SIZE];
__device__ __align__(16) float g_D2 [(size_t)BATCH * SIZE];

// ---------------------------------------------------------------------------
// PTX helpers (target-portable, sm_80+)
// ---------------------------------------------------------------------------
__device__ __forceinline__ uint32_t smem_u32(const void* p) {
    uint32_t a;
    asm("{ .reg .u64 t; cvta.to.shared.u64 t, %1; cvt.u32.u64 %0, t; }"
        : "=r"(a) : "l"(p));
    return a;
}

#define CP16(dst, src) \
    asm volatile("cp.async.cg.shared.global [%0], [%1], 16;" :: "r"(dst), "l"(src) : "memory")
#define CP_COMMIT() asm volatile("cp.async.commit_group;" ::: "memory")
#define CP_WAIT(n)  asm volatile("cp.async.wait_group %0;" :: "n"(n) : "memory")

#define LDSM4(r0, r1, r2, r3, a) \
    asm volatile("ldmatrix.sync.aligned.m8n8.x4.shared.b16 {%0,%1,%2,%3}, [%4];" \
                 : "=r"(r0), "=r"(r1), "=r"(r2), "=r"(r3) : "r"(a))

#define MMA16816(d, a, b) \
    asm volatile("mma.sync.aligned.m16n8k16.row.col.f32.f16.f16.f32 " \
                 "{%0,%1,%2,%3}, {%4,%5,%6,%7}, {%8,%9}, {%0,%1,%2,%3};" \
                 : "+f"((d)[0]), "+f"((d)[1]), "+f"((d)[2]), "+f"((d)[3]) \
                 : "r"((a)[0]), "r"((a)[1]), "r"((a)[2]), "r"((a)[3]), \
                   "r"((b)[0]), "r"((b)[1]))

// ---------------------------------------------------------------------------
// fp16 HGEMM:  C[M, Ntot] = act(A @ B^T + bias)
// A: [M, 1024] K-major fp16.  B: [Ntot, 1024] K-major fp16.
// CTA tile 128 x BN, BK=32, 4-stage cp.async pipeline, 256 threads.
// Warp grid 2(M) x 4(N): warp tile 64 x (BN/4).
// ---------------------------------------------------------------------------
template <int BN, bool RELU, bool OUTF16>
__global__ __launch_bounds__(256, 2) void mma_gemm(
    const f16* __restrict__ Ag, const f16* __restrict__ Bg,
    const float* __restrict__ bias,
    float* __restrict__ Cf, f16* __restrict__ Ch,
    int Ntot)
{
    constexpr int BM = 128, S = 4;
    constexpr int NCHUNK = D_IN / 32;             // 32 k-chunks of 32
    constexpr int ROWP = 40;                      // f16/row: 32 data + 8 pad
    constexpr int AE = BM * ROWP;                 // f16 in A tile
    constexpr int BE = BN * ROWP;
    constexpr int STAGE = AE + BE;                // f16 per stage
    constexpr int ACH = BM * 4;                   // 16B chunks in A tile
    constexpr int BCH = BN * 4;
    constexpr int NCHK = ACH + BCH;               // chunks per stage
    constexpr int NFRAG = BN / 32;                // n-frags per warp (4 or 2)
    constexpr int WNT = BN / 4;                   // warp n-tile

    extern __shared__ __align__(16) f16 sm[];

    const int tid = threadIdx.x, lane = tid & 31, wid = tid >> 5;
    const int warp_m = wid & 1, warp_n = wid >> 1;
    const int m0 = blockIdx.y * BM, n0 = blockIdx.x * BN;
    const uint32_t sbase = smem_u32(sm);

    auto issue_stage = [&](int i) {
        const int k0 = i * 32;
        const uint32_t sb = sbase + (uint32_t)(i % S) * STAGE * 2;
#pragma unroll
        for (int p = 0; p < (NCHK + 255) / 256; p++) {
            int c = tid + p * 256;
            if (c < NCHK) {
                const f16* g;
                uint32_t soff;
                if (c < ACH) {
                    int r = c >> 2, kc = c & 3;
                    g = Ag + (size_t)(m0 + r) * D_IN + k0 + kc * 8;
                    soff = (uint32_t)(r * ROWP + kc * 8);
                } else {
                    int cc = c - ACH, r = cc >> 2, kc = cc & 3;
                    g = Bg + (size_t)(n0 + r) * D_IN + k0 + kc * 8;
                    soff = (uint32_t)(AE + r * ROWP + kc * 8);
                }
                CP16(sb + soff * 2, (const char*)g);
            }
        }
    };

    float acc[4][NFRAG][4];
#pragma unroll
    for (int f = 0; f < 4; f++)
#pragma unroll
        for (int n = 0; n < NFRAG; n++)
#pragma unroll
            for (int q = 0; q < 4; q++) acc[f][n][q] = 0.f;

    const int aRow = warp_m * 64 + (lane & 15);
    const int aKl  = (lane >> 4) << 3;
    const int bRow = warp_n * WNT + (lane & 7) + ((lane >> 4) << 3);
    const int bKl  = ((lane >> 3) & 1) << 3;

#pragma unroll
    for (int i = 0; i < S - 1; i++) { issue_stage(i); CP_COMMIT(); }

    for (int i = 0; i < NCHUNK; i++) {
        CP_WAIT(S - 2);
        __syncthreads();

        if (i + S - 1 < NCHUNK) issue_stage(i + S - 1);
        CP_COMMIT();

        const uint32_t sb = sbase + (uint32_t)(i % S) * STAGE * 2;
#pragma unroll
        for (int k16 = 0; k16 < 32; k16 += 16) {
            uint32_t bh[NFRAG][2];
#pragma unroll
            for (int p = 0; p < NFRAG / 2; p++) {
                uint32_t rb = sb + (uint32_t)(AE + (bRow + p * 16) * ROWP + k16 + bKl) * 2;
                LDSM4(bh[2 * p][0], bh[2 * p][1], bh[2 * p + 1][0], bh[2 * p + 1][1], rb);
            }
#pragma unroll
            for (int f = 0; f < 4; f++) {
                uint32_t ah[4];
                uint32_t ra = sb + (uint32_t)(((aRow + f * 16) * ROWP) + k16 + aKl) * 2;
                LDSM4(ah[0], ah[1], ah[2], ah[3], ra);
#pragma unroll
                for (int n = 0; n < NFRAG; n++)
                    MMA16816(acc[f][n], ah, bh[n]);
            }
        }
    }

    // ---- epilogue: stage C through smem for coalesced stores ----
    __syncthreads();
    constexpr int P = BN + 4;
    float* smC = reinterpret_cast<float*>(sm);
#pragma unroll
    for (int f = 0; f < 4; f++)
#pragma unroll
        for (int n = 0; n < NFRAG; n++) {
            int r = warp_m * 64 + f * 16 + (lane >> 2);
            int c = warp_n * WNT + n * 8 + 2 * (lane & 3);
            *reinterpret_cast<float2*>(&smC[r * P + c]) =
                make_float2(acc[f][n][0], acc[f][n][1]);
            *reinterpret_cast<float2*>(&smC[(r + 8) * P + c]) =
                make_float2(acc[f][n][2], acc[f][n][3]);
        }
    __syncthreads();

    constexpr int C4 = BN / 4;
#pragma unroll
    for (int u = 0; u < BM * C4 / 256; u++) {
        int idx = tid + u * 256;
        int r = idx / C4, c4 = idx % C4;
        float4 v = *reinterpret_cast<float4*>(&smC[r * P + c4 * 4]);
        int col = n0 + c4 * 4;
        v.x += bias[col]; v.y += bias[col + 1]; v.z += bias[col + 2]; v.w += bias[col + 3];
        if (RELU) {
            v.x = fmaxf(v.x, 0.f); v.y = fmaxf(v.y, 0.f);
            v.z = fmaxf(v.z, 0.f); v.w = fmaxf(v.w, 0.f);
        }
        size_t go = (size_t)(m0 + r) * Ntot + col;
        if (OUTF16) {
            __half2 a = __halves2half2(__float2half(v.x), __float2half(v.y));
            __half2 b = __halves2half2(__float2half(v.z), __float2half(v.w));
            *reinterpret_cast<__half2*>(Ch + go)     = a;
            *reinterpret_cast<__half2*>(Ch + go + 2) = b;
        } else {
            *reinterpret_cast<float4*>(Cf + go) = v;
        }
    }
}

// ---------------------------------------------------------------------------
// fp32 -> fp16 convert (vectorized)
// ---------------------------------------------------------------------------
__global__ void convert_f16(const float4* __restrict__ src,
                            __half2* __restrict__ dst, int n4)
{
    int i = blockIdx.x * blockDim.x + threadIdx.x;
    if (i >= n4) return;
    float4 v = src[i];
    dst[2 * i]     = __halves2half2(__float2half(v.x), __float2half(v.y));
    dst[2 * i + 1] = __halves2half2(__float2half(v.z), __float2half(v.w));
}

// ---------------------------------------------------------------------------
// W [K, N] fp32  ->  Wt [N, K] fp16 (transpose + round)
// ---------------------------------------------------------------------------
__global__ void transpose_cvt(const float* __restrict__ W,
                              f16* __restrict__ T, int K, int N)
{
    __shared__ float t[32][33];
    const int n0 = blockIdx.x * 32, k0 = blockIdx.y * 32;
    const int tx = threadIdx.x, ty = threadIdx.y;     // 32 x 8
#pragma unroll
    for (int r = 0; r < 32; r += 8)
        t[ty + r][tx] = W[(size_t)(k0 + ty + r) * N + n0 + tx];
    __syncthreads();
#pragma unroll
    for (int r = 0; r < 32; r += 8) {
        size_t o = (size_t)(n0 + ty + r) * K + k0 + tx;
        T[o] = __float2half(t[tx][ty + r]);
    }
}

// ---------------------------------------------------------------------------
// softmax over 64-wide rows (one warp per row, 2 cols/lane)
// ---------------------------------------------------------------------------
__global__ void d2_softmax(const float* __restrict__ L, float* __restrict__ D2)
{
    const int row = (blockIdx.x * blockDim.x + threadIdx.x) >> 5;
    const int l = threadIdx.x & 31;
    float a = L[(size_t)row * SIZE + l];
    float b = L[(size_t)row * SIZE + l + 32];
    float m = fmaxf(a, b);
#pragma unroll
    for (int o = 16; o > 0; o >>= 1) m = fmaxf(m, __shfl_xor_sync(0xffffffffu, m, o));
    float ea = expf(a - m), eb = expf(b - m);
    float s = ea + eb;
#pragma unroll
    for (int o = 16; o > 0; o >>= 1) s += __shfl_xor_sync(0xffffffffu, s, o);
    float inv = 1.0f / s;
    D2[(size_t)row * SIZE + l]      = ea * inv;
    D2[(size_t)row * SIZE + l + 32] = eb * inv;
}

// ---------------------------------------------------------------------------
// Finalize: per row — softmax over 4096 logits, then out[y]=max_x min(p,d2)
// ---------------------------------------------------------------------------
__global__ __launch_bounds__(256) void finalize(
    const float* __restrict__ logits, const float* __restrict__ d2,
    float* __restrict__ out)
{
    __shared__ float sl[NN];
    __shared__ float sred[8];
    __shared__ float sd[SIZE];

    const int b = blockIdx.x, tid = threadIdx.x;
    const float4* lrow = (const float4*)(logits + (size_t)b * NN);

    float lm = -1e30f;
#pragma unroll
    for (int l = 0; l < 4; l++) {
        int j = tid + l * 256;
        float4 t = lrow[j];
        *(float4*)&sl[4 * j] = t;
        lm = fmaxf(lm, fmaxf(fmaxf(t.x, t.y), fmaxf(t.z, t.w)));
    }
#pragma unroll
    for (int o = 16; o > 0; o >>= 1) lm = fmaxf(lm, __shfl_xor_sync(0xffffffffu, lm, o));
    if ((tid & 31) == 0) sred[tid >> 5] = lm;
    __syncthreads();
    if (tid < 32) {
        float v2 = (tid < 8) ? sred[tid] : -1e30f;
#pragma unroll
        for (int o = 4; o > 0; o >>= 1) v2 = fmaxf(v2, __shfl_xor_sync(0xffffffffu, v2, o));
        if (tid == 0) sred[0] = v2;
    }
    __syncthreads();
    const float m = sred[0];
    __syncthreads();

    float ls = 0.f;
#pragma unroll
    for (int l = 0; l < 4; l++) {
        int j = tid + l * 256;
        float4 t = *(float4*)&sl[4 * j];
        t.x = expf(t.x - m); t.y = expf(t.y - m);
        t.z = expf(t.z - m); t.w = expf(t.w - m);
        *(float4*)&sl[4 * j] = t;
        ls += t.x + t.y + t.z + t.w;
    }
#pragma unroll
    for (int o = 16; o > 0; o >>= 1) ls += __shfl_xor_sync(0xffffffffu, ls, o);
    if ((tid & 31) == 0) sred[tid >> 5] = ls;
    __syncthreads();
    if (tid < 32) {
        float v2 = (tid < 8) ? sred[tid] : 0.f;
#pragma unroll
        for (int o = 4; o > 0; o >>= 1) v2 += __shfl_xor_sync(0xffffffffu, v2, o);
        if (tid == 0) sred[0] = v2;
    }
    if (tid < SIZE) sd[tid] = d2[(size_t)b * SIZE + tid];
    __syncthreads();
    const float inv = 1.0f / sred[0];

    if (tid < SIZE) {
        float best = -1e30f;
#pragma unroll 8
        for (int x = 0; x < SIZE; x++)
            best = fmaxf(best, fminf(sl[x * SIZE + tid] * inv, sd[x]));
        out[(size_t)b * SIZE + tid] = best;
    }
}

// ---------------------------------------------------------------------------
// Launch
// ---------------------------------------------------------------------------
extern "C" void kernel_launch(void* const* d_in, const int* in_sizes, int n_in,
                              void* d_out, int out_size)
{
    const float* x   = (const float*)d_in[0];
    const float* W1a = (const float*)d_in[1];
    const float* b1a = (const float*)d_in[2];
    const float* W2a = (const float*)d_in[3];
    const float* b2a = (const float*)d_in[4];
    const float* W1b = (const float*)d_in[5];
    const float* b1b = (const float*)d_in[6];
    const float* W2b = (const float*)d_in[7];
    const float* b2b = (const float*)d_in[8];
    float* out = (float*)d_out;

    f16 *X, *W1aT, *W1bT, *W2aT, *W2bT, *Ha, *Hb;
    float *Lg, *Dlog, *D2;
    cudaGetSymbolAddress((void**)&X, g_X);
    cudaGetSymbolAddress((void**)&W1aT, g_W1aT); cudaGetSymbolAddress((void**)&W1bT, g_W1bT);
    cudaGetSymbolAddress((void**)&W2aT, g_W2aT); cudaGetSymbolAddress((void**)&W2bT, g_W2bT);
    cudaGetSymbolAddress((void**)&Ha, g_Ha);     cudaGetSymbolAddress((void**)&Hb, g_Hb);
    cudaGetSymbolAddress((void**)&Lg, g_Lg);
    cudaGetSymbolAddress((void**)&Dlog, g_Dlog); cudaGetSymbolAddress((void**)&D2, g_D2);

    // dynamic smem: 4 stages of (128+BN)*40*2 bytes; epilogue needs 128*(BN+4)*4
    const int smem128 = 81920;   // max(4*20480, 128*132*4=67584)
    const int smem64  = 61440;   // max(4*15360, 128*68*4=34816)
    cudaFuncSetAttribute((const void*)mma_gemm<128, true,  true >,
                         cudaFuncAttributeMaxDynamicSharedMemorySize, smem128);
    cudaFuncSetAttribute((const void*)mma_gemm<128, false, false>,
                         cudaFuncAttributeMaxDynamicSharedMemorySize, smem128);
    cudaFuncSetAttribute((const void*)mma_gemm<64,  false, false>,
                         cudaFuncAttributeMaxDynamicSharedMemorySize, smem64);

    convert_f16<<<(BATCH * D_IN / 4 + 255) / 256, 256>>>(
        (const float4*)x, (__half2*)X, BATCH * D_IN / 4);

    transpose_cvt<<<dim3(D_IN / 32, D_IN / 32), dim3(32, 8)>>>(W1a, W1aT, D_IN, D_IN);
    transpose_cvt<<<dim3(D_IN / 32, D_IN / 32), dim3(32, 8)>>>(W1b, W1bT, D_IN, D_IN);
    transpose_cvt<<<dim3(NN   / 32, D_IN / 32), dim3(32, 8)>>>(W2a, W2aT, D_IN, NN);
    transpose_cvt<<<dim3(SIZE / 32, D_IN / 32), dim3(32, 8)>>>(W2b, W2bT, D_IN, SIZE);

    // layer 1 (both branches): relu, fp16 outputs
    mma_gemm<128, true, true><<<dim3(D_IN / 128, BATCH / 128), 256, smem128>>>(
        X, W1aT, b1a, nullptr, Ha, D_IN);
    mma_gemm<128, true, true><<<dim3(D_IN / 128, BATCH / 128), 256, smem128>>>(
        X, W1bT, b1b, nullptr, Hb, D_IN);

    // layer 2a: logits [8192, 4096] fp32
    mma_gemm<128, false, false><<<dim3(NN / 128, BATCH / 128), 256, smem128>>>(
        Ha, W2aT, b2a, Lg, nullptr, NN);

    // layer 2b: d2 logits [8192, 64] fp32
    mma_gemm<64, false, false><<<dim3(1, BATCH / 128), 256, smem64>>>(
        Hb, W2bT, b2b, Dlog, nullptr, SIZE);

    d2_softmax<<<BATCH * 32 / 256, 256>>>(Dlog, D2);
    finalize<<<BATCH, 256>>>(Lg, D2, out);
}

// round 7
// speedup vs baseline: 5.4360x; 1.0003x over previous
#include <cuda_runtime.h>
#include <cuda_fp16.h>
#include <math.h>
#include <stdint.h>

#define BATCH 8192
#define D_IN  1024
#define SIZE  64
#define NN    4096

typedef __half  f16;

// ---------------------------------------------------------------------------
// Scratch (__device__ globals; no allocation allowed)
// ---------------------------------------------------------------------------
__device__ __align__(16) f16 g_X  [(size_t)BATCH * D_IN];
__device__ __align__(16) f16 g_W1aT[(size_t)D_IN * D_IN];
__device__ __align__(16) f16 g_W1bT[(size_t)D_IN * D_IN];
__device__ __align__(16) f16 g_W2aT[(size_t)NN * D_IN];
__device__ __align__(16) f16 g_W2bT[(size_t)SIZE * D_IN];
__device__ __align__(16) f16 g_Ha [(size_t)BATCH * D_IN];
__device__ __align__(16) f16 g_Hb [(size_t)BATCH * D_IN];
__device__ __align__(16) float g_Lg [(size_t)BATCH * NN];
__device__ __align__(16) float g_Dlog[(size_t)BATCH * SIZE];
__device__ __align__(16) float g_D2 [(size_t)BATCH * SIZE];

// ---------------------------------------------------------------------------
// PTX helpers (target-portable, sm_80+)
// ---------------------------------------------------------------------------
__device__ __forceinline__ uint32_t smem_u32(const void* p) {
    uint32_t a;
    asm("{ .reg .u64 t; cvta.to.shared.u64 t, %1; cvt.u32.u64 %0, t; }"
        : "=r"(a) : "l"(p));
    return a;
}

#define CP16(dst, src) \
    asm volatile("cp.async.cg.shared.global [%0], [%1], 16;" :: "r"(dst), "l"(src) : "memory")
#define CP_COMMIT() asm volatile("cp.async.commit_group;" ::: "memory")
#define CP_WAIT(n)  asm volatile("cp.async.wait_group %0;" :: "n"(n) : "memory")

#define LDSM4(r0, r1, r2, r3, a) \
    asm volatile("ldmatrix.sync.aligned.m8n8.x4.shared.b16 {%0,%1,%2,%3}, [%4];" \
                 : "=r"(r0), "=r"(r1), "=r"(r2), "=r"(r3) : "r"(a))

#define MMA16816(d, a, b) \
    asm volatile("mma.sync.aligned.m16n8k16.row.col.f32.f16.f16.f32 " \
                 "{%0,%1,%2,%3}, {%4,%5,%6,%7}, {%8,%9}, {%0,%1,%2,%3};" \
                 : "+f"((d)[0]), "+f"((d)[1]), "+f"((d)[2]), "+f"((d)[3]) \
                 : "r"((a)[0]), "r"((a)[1]), "r"((a)[2]), "r"((a)[3]), \
                   "r"((b)[0]), "r"((b)[1]))

// ---------------------------------------------------------------------------
// fp16 HGEMM:  C[M, Ntot] = act(A @ B^T + bias)
// A: [M, 1024] K-major fp16.  B: [Ntot, 1024] K-major fp16.
// CTA tile 128 x BN, BK=32, 4-stage cp.async pipeline, 256 threads.
// Warp grid 2(M) x 4(N): warp tile 64 x (BN/4).
// ---------------------------------------------------------------------------
template <int BN, bool RELU, bool OUTF16>
__global__ __launch_bounds__(256, 2) void mma_gemm(
    const f16* __restrict__ Ag, const f16* __restrict__ Bg,
    const float* __restrict__ bias,
    float* __restrict__ Cf, f16* __restrict__ Ch,
    int Ntot)
{
    constexpr int BM = 128, S = 4;
    constexpr int NCHUNK = D_IN / 32;             // 32 k-chunks of 32
    constexpr int ROWP = 40;                      // f16/row: 32 data + 8 pad
    constexpr int AE = BM * ROWP;                 // f16 in A tile
    constexpr int BE = BN * ROWP;
    constexpr int STAGE = AE + BE;                // f16 per stage
    constexpr int ACH = BM * 4;                   // 16B chunks in A tile
    constexpr int BCH = BN * 4;
    constexpr int NCHK = ACH + BCH;               // chunks per stage
    constexpr int NFRAG = BN / 32;                // n-frags per warp (4 or 2)
    constexpr int WNT = BN / 4;                   // warp n-tile

    extern __shared__ __align__(16) f16 sm[];

    const int tid = threadIdx.x, lane = tid & 31, wid = tid >> 5;
    const int warp_m = wid & 1, warp_n = wid >> 1;
    const int m0 = blockIdx.y * BM, n0 = blockIdx.x * BN;
    const uint32_t sbase = smem_u32(sm);

    auto issue_stage = [&](int i) {
        const int k0 = i * 32;
        const uint32_t sb = sbase + (uint32_t)(i % S) * STAGE * 2;
#pragma unroll
        for (int p = 0; p < (NCHK + 255) / 256; p++) {
            int c = tid + p * 256;
            if (c < NCHK) {
                const f16* g;
                uint32_t soff;
                if (c < ACH) {
                    int r = c >> 2, kc = c & 3;
                    g = Ag + (size_t)(m0 + r) * D_IN + k0 + kc * 8;
                    soff = (uint32_t)(r * ROWP + kc * 8);
                } else {
                    int cc = c - ACH, r = cc >> 2, kc = cc & 3;
                    g = Bg + (size_t)(n0 + r) * D_IN + k0 + kc * 8;
                    soff = (uint32_t)(AE + r * ROWP + kc * 8);
                }
                CP16(sb + soff * 2, (const char*)g);
            }
        }
    };

    float acc[4][NFRAG][4];
#pragma unroll
    for (int f = 0; f < 4; f++)
#pragma unroll
        for (int n = 0; n < NFRAG; n++)
#pragma unroll
            for (int q = 0; q < 4; q++) acc[f][n][q] = 0.f;

    const int aRow = warp_m * 64 + (lane & 15);
    const int aKl  = (lane >> 4) << 3;
    const int bRow = warp_n * WNT + (lane & 7) + ((lane >> 4) << 3);
    const int bKl  = ((lane >> 3) & 1) << 3;

#pragma unroll
    for (int i = 0; i < S - 1; i++) { issue_stage(i); CP_COMMIT(); }

    for (int i = 0; i < NCHUNK; i++) {
        CP_WAIT(S - 2);
        __syncthreads();

        if (i + S - 1 < NCHUNK) issue_stage(i + S - 1);
        CP_COMMIT();

        const uint32_t sb = sbase + (uint32_t)(i % S) * STAGE * 2;
#pragma unroll
        for (int k16 = 0; k16 < 32; k16 += 16) {
            uint32_t bh[NFRAG][2];
#pragma unroll
            for (int p = 0; p < NFRAG / 2; p++) {
                uint32_t rb = sb + (uint32_t)(AE + (bRow + p * 16) * ROWP + k16 + bKl) * 2;
                LDSM4(bh[2 * p][0], bh[2 * p][1], bh[2 * p + 1][0], bh[2 * p + 1][1], rb);
            }
#pragma unroll
            for (int f = 0; f < 4; f++) {
                uint32_t ah[4];
                uint32_t ra = sb + (uint32_t)(((aRow + f * 16) * ROWP) + k16 + aKl) * 2;
                LDSM4(ah[0], ah[1], ah[2], ah[3], ra);
#pragma unroll
                for (int n = 0; n < NFRAG; n++)
                    MMA16816(acc[f][n], ah, bh[n]);
            }
        }
    }

    // ---- epilogue: stage C through smem for coalesced stores ----
    __syncthreads();
    constexpr int P = BN + 4;
    float* smC = reinterpret_cast<float*>(sm);
#pragma unroll
    for (int f = 0; f < 4; f++)
#pragma unroll
        for (int n = 0; n < NFRAG; n++) {
            int r = warp_m * 64 + f * 16 + (lane >> 2);
            int c = warp_n * WNT + n * 8 + 2 * (lane & 3);
            *reinterpret_cast<float2*>(&smC[r * P + c]) =
                make_float2(acc[f][n][0], acc[f][n][1]);
            *reinterpret_cast<float2*>(&smC[(r + 8) * P + c]) =
                make_float2(acc[f][n][2], acc[f][n][3]);
        }
    __syncthreads();

    constexpr int C4 = BN / 4;
#pragma unroll
    for (int u = 0; u < BM * C4 / 256; u++) {
        int idx = tid + u * 256;
        int r = idx / C4, c4 = idx % C4;
        float4 v = *reinterpret_cast<float4*>(&smC[r * P + c4 * 4]);
        int col = n0 + c4 * 4;
        v.x += bias[col]; v.y += bias[col + 1]; v.z += bias[col + 2]; v.w += bias[col + 3];
        if (RELU) {
            v.x = fmaxf(v.x, 0.f); v.y = fmaxf(v.y, 0.f);
            v.z = fmaxf(v.z, 0.f); v.w = fmaxf(v.w, 0.f);
        }
        size_t go = (size_t)(m0 + r) * Ntot + col;
        if (OUTF16) {
            __half2 a = __halves2half2(__float2half(v.x), __float2half(v.y));
            __half2 b = __halves2half2(__float2half(v.z), __float2half(v.w));
            *reinterpret_cast<__half2*>(Ch + go)     = a;
            *reinterpret_cast<__half2*>(Ch + go + 2) = b;
        } else {
            *reinterpret_cast<float4*>(Cf + go) = v;
        }
    }
}

// ---------------------------------------------------------------------------
// fp32 -> fp16 convert (vectorized)
// ---------------------------------------------------------------------------
__global__ void convert_f16(const float4* __restrict__ src,
                            __half2* __restrict__ dst, int n4)
{
    int i = blockIdx.x * blockDim.x + threadIdx.x;
    if (i >= n4) return;
    float4 v = src[i];
    dst[2 * i]     = __halves2half2(__float2half(v.x), __float2half(v.y));
    dst[2 * i + 1] = __halves2half2(__float2half(v.z), __float2half(v.w));
}

// ---------------------------------------------------------------------------
// W [K, N] fp32  ->  Wt [N, K] fp16 (transpose + round)
// ---------------------------------------------------------------------------
__global__ void transpose_cvt(const float* __restrict__ W,
                              f16* __restrict__ T, int K, int N)
{
    __shared__ float t[32][33];
    const int n0 = blockIdx.x * 32, k0 = blockIdx.y * 32;
    const int tx = threadIdx.x, ty = threadIdx.y;     // 32 x 8
#pragma unroll
    for (int r = 0; r < 32; r += 8)
        t[ty + r][tx] = W[(size_t)(k0 + ty + r) * N + n0 + tx];
    __syncthreads();
#pragma unroll
    for (int r = 0; r < 32; r += 8) {
        size_t o = (size_t)(n0 + ty + r) * K + k0 + tx;
        T[o] = __float2half(t[tx][ty + r]);
    }
}

// ---------------------------------------------------------------------------
// softmax over 64-wide rows (one warp per row, 2 cols/lane)
// ---------------------------------------------------------------------------
__global__ void d2_softmax(const float* __restrict__ L, float* __restrict__ D2)
{
    const int row = (blockIdx.x * blockDim.x + threadIdx.x) >> 5;
    const int l = threadIdx.x & 31;
    float a = L[(size_t)row * SIZE + l];
    float b = L[(size_t)row * SIZE + l + 32];
    float m = fmaxf(a, b);
#pragma unroll
    for (int o = 16; o > 0; o >>= 1) m = fmaxf(m, __shfl_xor_sync(0xffffffffu, m, o));
    float ea = expf(a - m), eb = expf(b - m);
    float s = ea + eb;
#pragma unroll
    for (int o = 16; o > 0; o >>= 1) s += __shfl_xor_sync(0xffffffffu, s, o);
    float inv = 1.0f / s;
    D2[(size_t)row * SIZE + l]      = ea * inv;
    D2[(size_t)row * SIZE + l + 32] = eb * inv;
}

// ---------------------------------------------------------------------------
// Finalize: per row — softmax over 4096 logits, then out[y]=max_x min(p,d2)
// ---------------------------------------------------------------------------
__global__ __launch_bounds__(256) void finalize(
    const float* __restrict__ logits, const float* __restrict__ d2,
    float* __restrict__ out)
{
    __shared__ float sl[NN];
    __shared__ float sred[8];
    __shared__ float sd[SIZE];

    const int b = blockIdx.x, tid = threadIdx.x;
    const float4* lrow = (const float4*)(logits + (size_t)b * NN);

    float lm = -1e30f;
#pragma unroll
    for (int l = 0; l < 4; l++) {
        int j = tid + l * 256;
        float4 t = lrow[j];
        *(float4*)&sl[4 * j] = t;
        lm = fmaxf(lm, fmaxf(fmaxf(t.x, t.y), fmaxf(t.z, t.w)));
    }
#pragma unroll
    for (int o = 16; o > 0; o >>= 1) lm = fmaxf(lm, __shfl_xor_sync(0xffffffffu, lm, o));
    if ((tid & 31) == 0) sred[tid >> 5] = lm;
    __syncthreads();
    if (tid < 32) {
        float v2 = (tid < 8) ? sred[tid] : -1e30f;
#pragma unroll
        for (int o = 4; o > 0; o >>= 1) v2 = fmaxf(v2, __shfl_xor_sync(0xffffffffu, v2, o));
        if (tid == 0) sred[0] = v2;
    }
    __syncthreads();
    const float m = sred[0];
    __syncthreads();

    float ls = 0.f;
#pragma unroll
    for (int l = 0; l < 4; l++) {
        int j = tid + l * 256;
        float4 t = *(float4*)&sl[4 * j];
        t.x = expf(t.x - m); t.y = expf(t.y - m);
        t.z = expf(t.z - m); t.w = expf(t.w - m);
        *(float4*)&sl[4 * j] = t;
        ls += t.x + t.y + t.z + t.w;
    }
#pragma unroll
    for (int o = 16; o > 0; o >>= 1) ls += __shfl_xor_sync(0xffffffffu, ls, o);
    if ((tid & 31) == 0) sred[tid >> 5] = ls;
    __syncthreads();
    if (tid < 32) {
        float v2 = (tid < 8) ? sred[tid] : 0.f;
#pragma unroll
        for (int o = 4; o > 0; o >>= 1) v2 += __shfl_xor_sync(0xffffffffu, v2, o);
        if (tid == 0) sred[0] = v2;
    }
    if (tid < SIZE) sd[tid] = d2[(size_t)b * SIZE + tid];
    __syncthreads();
    const float inv = 1.0f / sred[0];

    if (tid < SIZE) {
        float best = -1e30f;
#pragma unroll 8
        for (int x = 0; x < SIZE; x++)
            best = fmaxf(best, fminf(sl[x * SIZE + tid] * inv, sd[x]));
        out[(size_t)b * SIZE + tid] = best;
    }
}

// ---------------------------------------------------------------------------
// Launch
// ---------------------------------------------------------------------------
extern "C" void kernel_launch(void* const* d_in, const int* in_sizes, int n_in,
                              void* d_out, int out_size)
{
    const float* x   = (const float*)d_in[0];
    const float* W1a = (const float*)d_in[1];
    const float* b1a = (const float*)d_in[2];
    const float* W2a = (const float*)d_in[3];
    const float* b2a = (const float*)d_in[4];
    const float* W1b = (const float*)d_in[5];
    const float* b1b = (const float*)d_in[6];
    const float* W2b = (const float*)d_in[7];
    const float* b2b = (const float*)d_in[8];
    float* out = (float*)d_out;

    f16 *X, *W1aT, *W1bT, *W2aT, *W2bT, *Ha, *Hb;
    float *Lg, *Dlog, *D2;
    cudaGetSymbolAddress((void**)&X, g_X);
    cudaGetSymbolAddress((void**)&W1aT, g_W1aT); cudaGetSymbolAddress((void**)&W1bT, g_W1bT);
    cudaGetSymbolAddress((void**)&W2aT, g_W2aT); cudaGetSymbolAddress((void**)&W2bT, g_W2bT);
    cudaGetSymbolAddress((void**)&Ha, g_Ha);     cudaGetSymbolAddress((void**)&Hb, g_Hb);
    cudaGetSymbolAddress((void**)&Lg, g_Lg);
    cudaGetSymbolAddress((void**)&Dlog, g_Dlog); cudaGetSymbolAddress((void**)&D2, g_D2);

    // dynamic smem: 4 stages of (128+BN)*40*2 bytes; epilogue needs 128*(BN+4)*4
    const int smem128 = 81920;   // max(4*20480, 128*132*4=67584)
    const int smem64  = 61440;   // max(4*15360, 128*68*4=34816)
    cudaFuncSetAttribute((const void*)mma_gemm<128, true,  true >,
                         cudaFuncAttributeMaxDynamicSharedMemorySize, smem128);
    cudaFuncSetAttribute((const void*)mma_gemm<128, false, false>,
                         cudaFuncAttributeMaxDynamicSharedMemorySize, smem128);
    cudaFuncSetAttribute((const void*)mma_gemm<64,  false, false>,
                         cudaFuncAttributeMaxDynamicSharedMemorySize, smem64);

    convert_f16<<<(BATCH * D_IN / 4 + 255) / 256, 256>>>(
        (const float4*)x, (__half2*)X, BATCH * D_IN / 4);

    transpose_cvt<<<dim3(D_IN / 32, D_IN / 32), dim3(32, 8)>>>(W1a, W1aT, D_IN, D_IN);
    transpose_cvt<<<dim3(D_IN / 32, D_IN / 32), dim3(32, 8)>>>(W1b, W1bT, D_IN, D_IN);
    transpose_cvt<<<dim3(NN   / 32, D_IN / 32), dim3(32, 8)>>>(W2a, W2aT, D_IN, NN);
    transpose_cvt<<<dim3(SIZE / 32, D_IN / 32), dim3(32, 8)>>>(W2b, W2bT, D_IN, SIZE);

    // layer 1 (both branches): relu, fp16 outputs
    mma_gemm<128, true, true><<<dim3(D_IN / 128, BATCH / 128), 256, smem128>>>(
        X, W1aT, b1a, nullptr, Ha, D_IN);
    mma_gemm<128, true, true><<<dim3(D_IN / 128, BATCH / 128), 256, smem128>>>(
        X, W1bT, b1b, nullptr, Hb, D_IN);

    // layer 2a: logits [8192, 4096] fp32
    mma_gemm<128, false, false><<<dim3(NN / 128, BATCH / 128), 256, smem128>>>(
        Ha, W2aT, b2a, Lg, nullptr, NN);

    // layer 2b: d2 logits [8192, 64] fp32
    mma_gemm<64, false, false><<<dim3(1, BATCH / 128), 256, smem64>>>(
        Hb, W2bT, b2b, Dlog, nullptr, SIZE);

    d2_softmax<<<BATCH * 32 / 256, 256>>>(Dlog, D2);
    finalize<<<BATCH, 256>>>(Lg, D2, out);
}